// round 5
// baseline (speedup 1.0000x reference)
#include <cuda_runtime.h>
#include <cstdint>
#include <cstdio>

#define NMAX 50000
#define EMAX 600000
#define CDIV(a,b) (((a)+(b)-1)/(b))

// ---------------- scratch (device globals; no allocation allowed) ----------------
__device__ float d_h   [(size_t)NMAX*256];  // GEMM output of current layer
__device__ float d_g1  [(size_t)NMAX*64];
__device__ float d_g2  [(size_t)NMAX*64];
__device__ float d_a1  [(size_t)NMAX*256];
__device__ float d_a2  [(size_t)NMAX*64];
__device__ float d_s1  [(size_t)NMAX*64];
__device__ float d_s2  [(size_t)NMAX*64];
__device__ float d_agg [(size_t)NMAX*128];
__device__ float d_cat [(size_t)NMAX*192];
__device__ float d_fc1o[(size_t)NMAX*64];
__device__ float d_as  [(size_t)NMAX*4];
__device__ float d_ad  [(size_t)NMAX*4];
__device__ float d_emax[(size_t)NMAX*4];
__device__ float d_den [(size_t)NMAX*4];
__device__ float d_alph[(size_t)EMAX*4];
__device__ float d_deg [NMAX];
__device__ float d_dinv[NMAX];
__device__ float d_bnsum[64];
__device__ float d_bnsq [64];
__device__ float d_bnmean[64];
__device__ float d_bnvar [64];

// ---------------- helpers ----------------
__device__ __forceinline__ float lrelu(float x){ return x > 0.f ? x : 0.2f * x; }

__device__ __forceinline__ void atomicMaxFloat(float* addr, float val){
    int old = __float_as_int(*addr);
    while (__int_as_float(old) < val){
        int assumed = old;
        old = atomicCAS((int*)addr, assumed, __float_as_int(val));
        if (old == assumed) break;
    }
}

// ---------------- generic kernels ----------------
__global__ void fill_k(float* p, float v, int n){
    int i = blockIdx.x*blockDim.x + threadIdx.x;
    if (i < n) p[i] = v;
}

// C[M,F] = (accum? C : 0) + A[M,K] @ B[K,F] (+bias) (+relu)
__global__ void gemm_k(const float* __restrict__ A, const float* __restrict__ B,
                       float* __restrict__ C, const float* __restrict__ bias,
                       int M, int K, int F, int accum, int act)
{
    __shared__ float As[32][65];
    __shared__ float Bs[32][64];
    int bm = blockIdx.x * 64;
    int bn = blockIdx.y * 64;
    int tid = threadIdx.x;
    int tx = tid & 15, ty = tid >> 4;
    float acc[4][4];
#pragma unroll
    for (int i=0;i<4;i++)
#pragma unroll
        for (int j=0;j<4;j++) acc[i][j]=0.f;

    for (int k0=0; k0<K; k0+=32){
#pragma unroll
        for (int i=tid;i<64*32;i+=256){
            int m=i>>5, kk=i&31;
            float v=0.f;
            if (bm+m<M) v = A[(size_t)(bm+m)*K + k0+kk];
            As[kk][m]=v;
        }
#pragma unroll
        for (int i=tid;i<32*64;i+=256){
            int kk=i>>6, n=i&63;
            float v=0.f;
            if (bn+n<F) v = B[(size_t)(k0+kk)*F + bn+n];
            Bs[kk][n]=v;
        }
        __syncthreads();
#pragma unroll
        for (int kk=0;kk<32;kk++){
            float a[4],b[4];
#pragma unroll
            for (int i=0;i<4;i++) a[i]=As[kk][ty*4+i];
#pragma unroll
            for (int j=0;j<4;j++) b[j]=Bs[kk][tx*4+j];
#pragma unroll
            for (int i=0;i<4;i++)
#pragma unroll
                for (int j=0;j<4;j++) acc[i][j] += a[i]*b[j];
        }
        __syncthreads();
    }
#pragma unroll
    for (int i=0;i<4;i++){
        int m = bm + ty*4 + i;
        if (m >= M) continue;
#pragma unroll
        for (int j=0;j<4;j++){
            int n = bn + tx*4 + j;
            if (n >= F) continue;
            float v = acc[i][j];
            if (bias) v += bias[n];
            size_t off = (size_t)m*F + n;
            if (accum) v += C[off];
            if (act == 1) v = fmaxf(v, 0.f);
            C[off] = v;
        }
    }
}

// out[i] = act(x[i] + b[i%F]), act: 1 relu, 2 elu
__global__ void bias_act_k(float* x, const float* __restrict__ b, int n, int F, int act){
    int i = blockIdx.x*blockDim.x + threadIdx.x;
    if (i >= n) return;
    float v = x[i];
    if (b) v += b[i % F];
    if (act == 1) v = fmaxf(v, 0.f);
    else if (act == 2) v = v > 0.f ? v : expm1f(v);
    x[i] = v;
}

// ---------------- degree / norm ----------------
__global__ void count_deg_k(const int* __restrict__ dst, float* deg, int E){
    int i = blockIdx.x*blockDim.x + threadIdx.x;
    if (i < E) atomicAdd(&deg[dst[i]], 1.0f);
}
__global__ void dinv_k(const float* deg, float* dinv, int n){
    int i = blockIdx.x*blockDim.x + threadIdx.x;
    if (i < n) dinv[i] = rsqrtf(deg[i] + 1.0f);   // deg includes self-loop
}

// ---------------- GCN ----------------
__global__ void gcn_init_k(const float* __restrict__ h, const float* __restrict__ dinv,
                           float* out, int n, int F){
    int i = blockIdx.x*blockDim.x + threadIdx.x;
    if (i >= n*F) return;
    int node = i / F;
    float dv = dinv[node];
    out[i] = h[i] * dv * dv;
}
__global__ void gcn_edge_k(const float4* __restrict__ h, float* out,
                           const int* __restrict__ src, const int* __restrict__ dst,
                           const float* __restrict__ dinv, int E, int F4){
    int idx = blockIdx.x*blockDim.x + threadIdx.x;
    if (idx >= E*F4) return;
    int e = idx / F4, c = idx % F4;
    int s = src[e], d = dst[e];
    float nrm = dinv[s]*dinv[d];
    float4 hv = h[(size_t)s*F4 + c];
    float* o = out + ((size_t)d*F4 + c)*4;
    atomicAdd(o+0, hv.x*nrm); atomicAdd(o+1, hv.y*nrm);
    atomicAdd(o+2, hv.z*nrm); atomicAdd(o+3, hv.w*nrm);
}

// ---------------- GAT ----------------
__global__ void gat_scal_k(const float* __restrict__ h, const float* __restrict__ asrc,
                           const float* __restrict__ adst, float* as_, float* ad_,
                           int n, int H, int C){
    int idx = blockIdx.x*blockDim.x + threadIdx.x;
    if (idx >= n*H) return;
    int node = idx / H, hh = idx % H;
    const float* hp = h + (size_t)node*H*C + (size_t)hh*C;
    const float* ap = asrc + hh*C;
    const float* bp = adst + hh*C;
    float s=0.f, d=0.f;
#pragma unroll 8
    for (int c=0;c<C;c++){ float v=hp[c]; s += v*ap[c]; d += v*bp[c]; }
    as_[idx]=s; ad_[idx]=d;
}
__global__ void gat_init_max_k(const float* as_, const float* ad_, float* emax, int nH){
    int i = blockIdx.x*blockDim.x + threadIdx.x;
    if (i < nH) emax[i] = lrelu(as_[i] + ad_[i]);   // self-loop term
}
__global__ void gat_edge_max_k(const int* __restrict__ src, const int* __restrict__ dst,
                               const float* __restrict__ as_, const float* __restrict__ ad_,
                               float* emax, int E, int H){
    int idx = blockIdx.x*blockDim.x + threadIdx.x;
    if (idx >= E*H) return;
    int e = idx / H, hh = idx % H;
    int s = src[e], d = dst[e];
    float ev = lrelu(as_[s*H+hh] + ad_[d*H+hh]);
    atomicMaxFloat(&emax[d*H+hh], ev);
}
__global__ void gat_init_den_k(const float* as_, const float* ad_, const float* emax,
                               float* den, int nH){
    int i = blockIdx.x*blockDim.x + threadIdx.x;
    if (i < nH) den[i] = expf(lrelu(as_[i] + ad_[i]) - emax[i]);
}
__global__ void gat_edge_ex_k(const int* __restrict__ src, const int* __restrict__ dst,
                              const float* __restrict__ as_, const float* __restrict__ ad_,
                              const float* __restrict__ emax, float* den, float* alpha,
                              int E, int H){
    int idx = blockIdx.x*blockDim.x + threadIdx.x;
    if (idx >= E*H) return;
    int e = idx / H, hh = idx % H;
    int s = src[e], d = dst[e];
    float ev = lrelu(as_[s*H+hh] + ad_[d*H+hh]);
    float ex = expf(ev - emax[d*H+hh]);
    alpha[idx] = ex;
    atomicAdd(&den[d*H+hh], ex);
}
__global__ void gat_alpha_div_k(const int* __restrict__ dst, const float* __restrict__ den,
                                float* alpha, int E, int H){
    int idx = blockIdx.x*blockDim.x + threadIdx.x;
    if (idx >= E*H) return;
    int e = idx / H, hh = idx % H;
    alpha[idx] /= (den[dst[e]*H+hh] + 1e-16f);
}
__global__ void gat_init_out_k(const float4* __restrict__ h, const float* __restrict__ as_,
                               const float* __restrict__ ad_, const float* __restrict__ emax,
                               const float* __restrict__ den, float4* out,
                               int n, int H, int C4){
    int idx = blockIdx.x*blockDim.x + threadIdx.x;
    if (idx >= n*H*C4) return;
    int node = idx / (H*C4);
    int r = idx % (H*C4);
    int hh = r / C4;
    float e = lrelu(as_[node*H+hh] + ad_[node*H+hh]);
    float w = expf(e - emax[node*H+hh]) / (den[node*H+hh] + 1e-16f);
    float4 hv = h[idx];
    out[idx] = make_float4(hv.x*w, hv.y*w, hv.z*w, hv.w*w);
}
__global__ void gat_edge_out_k(const int* __restrict__ src, const int* __restrict__ dst,
                               const float* __restrict__ alpha, const float4* __restrict__ h,
                               float* out, int E, int H, int C4){
    int idx = blockIdx.x*blockDim.x + threadIdx.x;
    if (idx >= E*H*C4) return;
    int e = idx / (H*C4);
    int r = idx % (H*C4);
    int hh = r / C4, c = r % C4;
    float w = alpha[e*H+hh];
    int s = src[e], d = dst[e];
    float4 hv = h[(size_t)s*H*C4 + hh*C4 + c];
    float* o = out + (((size_t)d*H + hh)*C4 + c)*4;
    atomicAdd(o+0, hv.x*w); atomicAdd(o+1, hv.y*w);
    atomicAdd(o+2, hv.z*w); atomicAdd(o+3, hv.w*w);
}

// ---------------- SAGE ----------------
__global__ void sage_edge_k(const float4* __restrict__ x, float* agg,
                            const int* __restrict__ src, const int* __restrict__ dst,
                            int E, int F4){
    int idx = blockIdx.x*blockDim.x + threadIdx.x;
    if (idx >= E*F4) return;
    int e = idx / F4, c = idx % F4;
    int s = src[e], d = dst[e];
    float4 v = x[(size_t)s*F4 + c];
    float* o = agg + ((size_t)d*F4 + c)*4;
    atomicAdd(o+0, v.x); atomicAdd(o+1, v.y);
    atomicAdd(o+2, v.z); atomicAdd(o+3, v.w);
}
__global__ void sage_div_k(float* agg, const float* __restrict__ deg, int n, int F){
    int i = blockIdx.x*blockDim.x + threadIdx.x;
    if (i >= n*F) return;
    agg[i] /= fmaxf(deg[i / F], 1.0f);
}

// ---------------- BatchNorm ----------------
__global__ void bn_stats_k(const float* __restrict__ x, float* gsum, float* gsq, int total){
    __shared__ float ss[256];
    __shared__ float sq[256];
    int tid = threadIdx.x;
    float s = 0.f, q = 0.f;
    for (int i = blockIdx.x*256 + tid; i < total; i += gridDim.x*256){
        float v = x[i];
        s += v; q += v*v;
    }
    ss[tid] = s; sq[tid] = q;
    __syncthreads();
    if (tid < 64){
        int c = tid & 63;   // stride gridDim*256 is a multiple of 64 -> channel fixed per thread
        float ts = ss[tid] + ss[tid+64] + ss[tid+128] + ss[tid+192];
        float tq = sq[tid] + sq[tid+64] + sq[tid+128] + sq[tid+192];
        atomicAdd(&gsum[c], ts);
        atomicAdd(&gsq[c], tq);
    }
}
__global__ void bn_final_k(const float* gsum, const float* gsq, float* mean, float* var, int n){
    int c = threadIdx.x;
    if (c < 64){
        float m = gsum[c] / (float)n;
        mean[c] = m;
        var[c] = gsq[c] / (float)n - m*m;
    }
}
__global__ void bn_apply_k(const float* __restrict__ x, const float* __restrict__ mean,
                           const float* __restrict__ var, const float* __restrict__ g,
                           const float* __restrict__ b, float* cat, int n, int off){
    int i = blockIdx.x*blockDim.x + threadIdx.x;
    if (i >= n*64) return;
    int c = i & 63;
    float v = (x[i] - mean[c]) * rsqrtf(var[c] + 1e-5f) * g[c] + b[c];
    cat[(size_t)(i >> 6)*192 + off + c] = v;
}

// ---------------- host orchestration ----------------
static inline float* sym(const void* s){
    void* p = nullptr;
    cudaGetSymbolAddress(&p, s);
    return (float*)p;
}

extern "C" void kernel_launch(void* const* d_in, const int* in_sizes, int n_in,
                              void* d_out, int out_size)
{
    const float* x        = (const float*)d_in[0];
    const int*   eidx     = (const int*)  d_in[1];
    const float* gcn1_w   = (const float*)d_in[2];
    const float* gcn1_b   = (const float*)d_in[3];
    const float* gcn2_w   = (const float*)d_in[4];
    const float* gcn2_b   = (const float*)d_in[5];
    const float* gat1_w   = (const float*)d_in[6];
    const float* gat1_as  = (const float*)d_in[7];
    const float* gat1_ad  = (const float*)d_in[8];
    const float* gat1_b   = (const float*)d_in[9];
    const float* gat2_w   = (const float*)d_in[10];
    const float* gat2_as  = (const float*)d_in[11];
    const float* gat2_ad  = (const float*)d_in[12];
    const float* gat2_b   = (const float*)d_in[13];
    const float* sage1_wl = (const float*)d_in[14];
    const float* sage1_bl = (const float*)d_in[15];
    const float* sage1_wr = (const float*)d_in[16];
    const float* sage2_wl = (const float*)d_in[17];
    const float* sage2_bl = (const float*)d_in[18];
    const float* sage2_wr = (const float*)d_in[19];
    const float* bng_g    = (const float*)d_in[20];
    const float* bng_b    = (const float*)d_in[21];
    const float* bna_g    = (const float*)d_in[22];
    const float* bna_b    = (const float*)d_in[23];
    const float* bns_g    = (const float*)d_in[24];
    const float* bns_b    = (const float*)d_in[25];
    const float* fc1_w    = (const float*)d_in[26];
    const float* fc1_b    = (const float*)d_in[27];
    const float* fc2_w    = (const float*)d_in[28];
    const float* fc2_b    = (const float*)d_in[29];
    float* out = (float*)d_out;

    const int n = in_sizes[0] / 128;
    const int E = in_sizes[1] / 2;
    const int* src = eidx;
    const int* dst = eidx + E;

    float* h    = sym(d_h);
    float* g1   = sym(d_g1);
    float* g2   = sym(d_g2);
    float* a1   = sym(d_a1);
    float* a2   = sym(d_a2);
    float* s1   = sym(d_s1);
    float* s2   = sym(d_s2);
    float* agg  = sym(d_agg);
    float* cat  = sym(d_cat);
    float* fc1o = sym(d_fc1o);
    float* as_  = sym(d_as);
    float* ad_  = sym(d_ad);
    float* emax = sym(d_emax);
    float* den  = sym(d_den);
    float* alph = sym(d_alph);
    float* deg  = sym(d_deg);
    float* dinv = sym(d_dinv);
    float* bsum = sym(d_bnsum);
    float* bsq  = sym(d_bnsq);
    float* bmean= sym(d_bnmean);
    float* bvar = sym(d_bnvar);

    const int T = 256;
    auto B = [](int cnt){ return dim3(CDIV(cnt, 256)); };

    // ---- degrees ----
    fill_k<<<B(n), T>>>(deg, 0.f, n);
    count_deg_k<<<B(E), T>>>(dst, deg, E);
    dinv_k<<<B(n), T>>>(deg, dinv, n);

    // ---- GCN layer 1: x[128] -> 64 ----
    {
        dim3 g(CDIV(n,64), 1);
        gemm_k<<<g, T>>>(x, gcn1_w, h, nullptr, n, 128, 64, 0, 0);
        gcn_init_k<<<B(n*64), T>>>(h, dinv, g1, n, 64);
        gcn_edge_k<<<B(E*16), T>>>((const float4*)h, g1, src, dst, dinv, E, 16);
        bias_act_k<<<B(n*64), T>>>(g1, gcn1_b, n*64, 64, 1);
    }
    // ---- GCN layer 2: 64 -> 64 ----
    {
        dim3 g(CDIV(n,64), 1);
        gemm_k<<<g, T>>>(g1, gcn2_w, h, nullptr, n, 64, 64, 0, 0);
        gcn_init_k<<<B(n*64), T>>>(h, dinv, g2, n, 64);
        gcn_edge_k<<<B(E*16), T>>>((const float4*)h, g2, src, dst, dinv, E, 16);
        bias_act_k<<<B(n*64), T>>>(g2, gcn2_b, n*64, 64, 1);
    }
    // BN(gcn) -> cat[:,0:64]
    fill_k<<<1, 64>>>(bsum, 0.f, 64);
    fill_k<<<1, 64>>>(bsq, 0.f, 64);
    bn_stats_k<<<256, T>>>(g2, bsum, bsq, n*64);
    bn_final_k<<<1, 64>>>(bsum, bsq, bmean, bvar, n);
    bn_apply_k<<<B(n*64), T>>>(g2, bmean, bvar, bng_g, bng_b, cat, n, 0);

    // ---- GAT layer 1: x[128] -> 4 heads x 64 (concat) ----
    {
        const int H = 4, C = 64, C4 = 16;
        dim3 g(CDIV(n,64), CDIV(H*C,64));
        gemm_k<<<g, T>>>(x, gat1_w, h, nullptr, n, 128, H*C, 0, 0);
        gat_scal_k<<<B(n*H), T>>>(h, gat1_as, gat1_ad, as_, ad_, n, H, C);
        gat_init_max_k<<<B(n*H), T>>>(as_, ad_, emax, n*H);
        gat_edge_max_k<<<B(E*H), T>>>(src, dst, as_, ad_, emax, E, H);
        gat_init_den_k<<<B(n*H), T>>>(as_, ad_, emax, den, n*H);
        gat_edge_ex_k<<<B(E*H), T>>>(src, dst, as_, ad_, emax, den, alph, E, H);
        gat_alpha_div_k<<<B(E*H), T>>>(dst, den, alph, E, H);
        gat_init_out_k<<<B(n*H*C4), T>>>((const float4*)h, as_, ad_, emax, den,
                                         (float4*)a1, n, H, C4);
        gat_edge_out_k<<<B(E*H*C4), T>>>(src, dst, alph, (const float4*)h, a1, E, H, C4);
        bias_act_k<<<B(n*H*C), T>>>(a1, gat1_b, n*H*C, H*C, 2);
    }
    // ---- GAT layer 2: 256 -> 1 head x 64 ----
    {
        const int H = 1, C = 64, C4 = 16;
        dim3 g(CDIV(n,64), 1);
        gemm_k<<<g, T>>>(a1, gat2_w, h, nullptr, n, 256, 64, 0, 0);
        gat_scal_k<<<B(n*H), T>>>(h, gat2_as, gat2_ad, as_, ad_, n, H, C);
        gat_init_max_k<<<B(n*H), T>>>(as_, ad_, emax, n*H);
        gat_edge_max_k<<<B(E*H), T>>>(src, dst, as_, ad_, emax, E, H);
        gat_init_den_k<<<B(n*H), T>>>(as_, ad_, emax, den, n*H);
        gat_edge_ex_k<<<B(E*H), T>>>(src, dst, as_, ad_, emax, den, alph, E, H);
        gat_alpha_div_k<<<B(E*H), T>>>(dst, den, alph, E, H);
        gat_init_out_k<<<B(n*H*C4), T>>>((const float4*)h, as_, ad_, emax, den,
                                         (float4*)a2, n, H, C4);
        gat_edge_out_k<<<B(E*H*C4), T>>>(src, dst, alph, (const float4*)h, a2, E, H, C4);
        bias_act_k<<<B(n*C), T>>>(a2, gat2_b, n*C, C, 2);
    }
    // BN(gat) -> cat[:,64:128]
    fill_k<<<1, 64>>>(bsum, 0.f, 64);
    fill_k<<<1, 64>>>(bsq, 0.f, 64);
    bn_stats_k<<<256, T>>>(a2, bsum, bsq, n*64);
    bn_final_k<<<1, 64>>>(bsum, bsq, bmean, bvar, n);
    bn_apply_k<<<B(n*64), T>>>(a2, bmean, bvar, bna_g, bna_b, cat, n, 64);

    // ---- SAGE layer 1: x[128] -> 64 ----
    {
        fill_k<<<B(n*128), T>>>(agg, 0.f, n*128);
        sage_edge_k<<<B(E*32), T>>>((const float4*)x, agg, src, dst, E, 32);
        sage_div_k<<<B(n*128), T>>>(agg, deg, n, 128);
        dim3 g(CDIV(n,64), 1);
        gemm_k<<<g, T>>>(agg, sage1_wl, s1, sage1_bl, n, 128, 64, 0, 0);
        gemm_k<<<g, T>>>(x, sage1_wr, s1, nullptr, n, 128, 64, 1, 1);  // accum + relu
    }
    // ---- SAGE layer 2: 64 -> 64 ----
    {
        fill_k<<<B(n*64), T>>>(agg, 0.f, n*64);
        sage_edge_k<<<B(E*16), T>>>((const float4*)s1, agg, src, dst, E, 16);
        sage_div_k<<<B(n*64), T>>>(agg, deg, n, 64);
        dim3 g(CDIV(n,64), 1);
        gemm_k<<<g, T>>>(agg, sage2_wl, s2, sage2_bl, n, 64, 64, 0, 0);
        gemm_k<<<g, T>>>(s1, sage2_wr, s2, nullptr, n, 64, 64, 1, 1);  // accum + relu
    }
    // BN(sage) -> cat[:,128:192]
    fill_k<<<1, 64>>>(bsum, 0.f, 64);
    fill_k<<<1, 64>>>(bsq, 0.f, 64);
    bn_stats_k<<<256, T>>>(s2, bsum, bsq, n*64);
    bn_final_k<<<1, 64>>>(bsum, bsq, bmean, bvar, n);
    bn_apply_k<<<B(n*64), T>>>(s2, bmean, bvar, bns_g, bns_b, cat, n, 128);

    // ---- MLP head ----
    {
        dim3 g1_(CDIV(n,64), 1);
        gemm_k<<<g1_, T>>>(cat, fc1_w, fc1o, fc1_b, n, 192, 64, 0, 1);   // relu
        gemm_k<<<g1_, T>>>(fc1o, fc2_w, out, fc2_b, n, 64, 2, 0, 0);
    }
}

// round 6
// speedup vs baseline: 2.6930x; 2.6930x over previous
#include <cuda_runtime.h>
#include <cstdint>
#include <cstdio>

#define NMAX 50000
#define EMAX 600000
#define CDIV(a,b) (((a)+(b)-1)/(b))

// ---------------- scratch (device globals; no allocation allowed) ----------------
__device__ __align__(16) float d_h   [(size_t)NMAX*256];
__device__ __align__(16) float d_g1  [(size_t)NMAX*64];
__device__ __align__(16) float d_g2  [(size_t)NMAX*64];
__device__ __align__(16) float d_a1  [(size_t)NMAX*256];
__device__ __align__(16) float d_a2  [(size_t)NMAX*64];
__device__ __align__(16) float d_s1  [(size_t)NMAX*64];
__device__ __align__(16) float d_s2  [(size_t)NMAX*64];
__device__ __align__(16) float d_hl  [(size_t)NMAX*64];
__device__ __align__(16) float d_cat [(size_t)NMAX*192];
__device__ __align__(16) float d_fc1o[(size_t)NMAX*64];
__device__ __align__(16) float d_as  [(size_t)NMAX*4];
__device__ __align__(16) float d_ad  [(size_t)NMAX*4];
__device__ float d_dinv[NMAX];
__device__ int   d_cnt [NMAX];
__device__ int   d_rp  [NMAX+1];
__device__ int   d_cur [NMAX];
__device__ int   d_ci  [EMAX];
__device__ float d_bnsum[64];
__device__ float d_bnsq [64];
__device__ float d_bnmean[64];
__device__ float d_bnvar [64];

// ---------------- helpers ----------------
__device__ __forceinline__ float lrelu(float x){ return x > 0.f ? x : 0.2f * x; }
__device__ __forceinline__ float elu(float x){ return x > 0.f ? x : expm1f(x); }

// ---------------- CSR build ----------------
__global__ void izero_k(int* p, int n){
    int i = blockIdx.x*blockDim.x + threadIdx.x;
    if (i < n) p[i] = 0;
}
__global__ void icopy_k(const int* __restrict__ a, int* b, int n){
    int i = blockIdx.x*blockDim.x + threadIdx.x;
    if (i < n) b[i] = a[i];
}
__global__ void hist_k(const int* __restrict__ dst, int* cnt, int E){
    int i = blockIdx.x*blockDim.x + threadIdx.x;
    if (i < E) atomicAdd(&cnt[dst[i]], 1);
}
// single-block exclusive scan: rp[0]=0, rp[i+1]=sum cnt[0..i]
__global__ void scan_k(const int* __restrict__ cnt, int* rp, int n){
    __shared__ int wsum[32];
    __shared__ int carry_s;
    int lane = threadIdx.x & 31, wid = threadIdx.x >> 5;
    if (threadIdx.x == 0){ carry_s = 0; rp[0] = 0; }
    __syncthreads();
    for (int base = 0; base < n; base += 1024){
        int i = base + threadIdx.x;
        int v = (i < n) ? cnt[i] : 0;
        int x = v;
#pragma unroll
        for (int o = 1; o < 32; o <<= 1){
            int t = __shfl_up_sync(0xffffffffu, x, o);
            if (lane >= o) x += t;
        }
        if (lane == 31) wsum[wid] = x;
        __syncthreads();
        if (wid == 0){
            int y = wsum[lane];
#pragma unroll
            for (int o = 1; o < 32; o <<= 1){
                int t = __shfl_up_sync(0xffffffffu, y, o);
                if (lane >= o) y += t;
            }
            wsum[lane] = y;
        }
        __syncthreads();
        int incl = x + (wid > 0 ? wsum[wid-1] : 0) + carry_s;
        if (i < n) rp[i+1] = incl;
        __syncthreads();
        if (threadIdx.x == 1023) carry_s = incl;
        __syncthreads();
    }
}
__global__ void csr_fill_k(const int* __restrict__ src, const int* __restrict__ dst,
                           int* cursor, int* ci, int E){
    int e = blockIdx.x*blockDim.x + threadIdx.x;
    if (e < E){
        int p = atomicAdd(&cursor[dst[e]], 1);
        ci[p] = src[e];
    }
}
__global__ void dinv_k(const int* __restrict__ cnt, float* dinv, int n){
    int i = blockIdx.x*blockDim.x + threadIdx.x;
    if (i < n) dinv[i] = rsqrtf((float)cnt[i] + 1.0f);  // +1 self-loop
}

// ---------------- GEMM: C[M,F] = A[M,K] @ B[K,F] (+bias)(+relu); K%32==0, F%64==0 ----
__global__ __launch_bounds__(256) void gemm128_k(
    const float* __restrict__ A, const float* __restrict__ B,
    float* __restrict__ C, const float* __restrict__ bias,
    int M, int K, int F, int act)
{
    __shared__ float As[32][132];
    __shared__ float Bs[32][64];
    int bm = blockIdx.x * 128;
    int bn = blockIdx.y * 64;
    int tid = threadIdx.x;
    int tx = tid & 15, ty = tid >> 4;
    float acc[8][4];
#pragma unroll
    for (int i=0;i<8;i++)
#pragma unroll
        for (int j=0;j<4;j++) acc[i][j]=0.f;

    for (int k0 = 0; k0 < K; k0 += 32){
        // A tile: 128x32, 1024 float4, 4/thread (thread covers row m=tid>>1)
#pragma unroll
        for (int i=0;i<4;i++){
            int l = tid*4 + i;
            int m = l >> 3, kq = l & 7;
            float4 v = make_float4(0.f,0.f,0.f,0.f);
            if (bm + m < M) v = *(const float4*)&A[(size_t)(bm+m)*K + k0 + kq*4];
            As[kq*4+0][m]=v.x; As[kq*4+1][m]=v.y; As[kq*4+2][m]=v.z; As[kq*4+3][m]=v.w;
        }
        // B tile: 32x64, 512 float4, 2/thread
#pragma unroll
        for (int i=0;i<2;i++){
            int l = tid*2 + i;
            int kk = l >> 4, nq = l & 15;
            float4 v = *(const float4*)&B[(size_t)(k0+kk)*F + bn + nq*4];
            *(float4*)&Bs[kk][nq*4] = v;
        }
        __syncthreads();
#pragma unroll
        for (int kk=0;kk<32;kk++){
            float4 a0 = *(const float4*)&As[kk][ty*8];
            float4 a1 = *(const float4*)&As[kk][ty*8+4];
            float4 b  = *(const float4*)&Bs[kk][tx*4];
            float av[8] = {a0.x,a0.y,a0.z,a0.w,a1.x,a1.y,a1.z,a1.w};
            float bv[4] = {b.x,b.y,b.z,b.w};
#pragma unroll
            for (int i=0;i<8;i++)
#pragma unroll
                for (int j=0;j<4;j++) acc[i][j] += av[i]*bv[j];
        }
        __syncthreads();
    }
    float bvals[4] = {0.f,0.f,0.f,0.f};
    if (bias){
#pragma unroll
        for (int j=0;j<4;j++) bvals[j] = bias[bn + tx*4 + j];
    }
#pragma unroll
    for (int i=0;i<8;i++){
        int m = bm + ty*8 + i;
        if (m >= M) continue;
        float4 o;
        o.x = acc[i][0]+bvals[0]; o.y = acc[i][1]+bvals[1];
        o.z = acc[i][2]+bvals[2]; o.w = acc[i][3]+bvals[3];
        if (act){
            o.x=fmaxf(o.x,0.f); o.y=fmaxf(o.y,0.f);
            o.z=fmaxf(o.z,0.f); o.w=fmaxf(o.w,0.f);
        }
        *(float4*)&C[(size_t)m*F + bn + tx*4] = o;
    }
}

// ---------------- fused gather kernels (warp per node) ----------------
// GCN: out = relu(dinv_d * (sum_s dinv_s*h_s + dinv_d*h_d) + b), F=64
__global__ void gcn_gather_k(const float* __restrict__ h, const float* __restrict__ dinv,
                             const int* __restrict__ rp, const int* __restrict__ ci,
                             const float* __restrict__ bias, float* __restrict__ out, int n)
{
    int w = (blockIdx.x*blockDim.x + threadIdx.x) >> 5;
    if (w >= n) return;
    int lane = threadIdx.x & 31;
    int beg = rp[w], end = rp[w+1];
    float dvd = dinv[w];
    float a0 = dvd * h[(size_t)w*64 + lane];
    float a1 = dvd * h[(size_t)w*64 + 32 + lane];
    for (int e = beg; e < end; e++){
        int s = ci[e];
        float ds = dinv[s];
        a0 += ds * h[(size_t)s*64 + lane];
        a1 += ds * h[(size_t)s*64 + 32 + lane];
    }
    float r0 = fmaxf(dvd*a0 + bias[lane], 0.f);
    float r1 = fmaxf(dvd*a1 + bias[32+lane], 0.f);
    out[(size_t)w*64 + lane] = r0;
    out[(size_t)w*64 + 32 + lane] = r1;
}

// SAGE: out = relu(mean_s(hl_s) + bl + xr_d), F=64 (linear commutes with mean)
__global__ void sage_gather_k(const float* __restrict__ hl, const float* __restrict__ xr,
                              const int* __restrict__ rp, const int* __restrict__ ci,
                              const float* __restrict__ bl, float* __restrict__ out, int n)
{
    int w = (blockIdx.x*blockDim.x + threadIdx.x) >> 5;
    if (w >= n) return;
    int lane = threadIdx.x & 31;
    int beg = rp[w], end = rp[w+1];
    float a0 = 0.f, a1 = 0.f;
    for (int e = beg; e < end; e++){
        int s = ci[e];
        a0 += hl[(size_t)s*64 + lane];
        a1 += hl[(size_t)s*64 + 32 + lane];
    }
    float inv = 1.f / fmaxf((float)(end - beg), 1.f);
    float r0 = fmaxf(a0*inv + bl[lane]      + xr[(size_t)w*64 + lane],      0.f);
    float r1 = fmaxf(a1*inv + bl[32+lane]   + xr[(size_t)w*64 + 32 + lane], 0.f);
    out[(size_t)w*64 + lane] = r0;
    out[(size_t)w*64 + 32 + lane] = r1;
}

// attention scalars: as_[i*H+h] = h_i,h . asrc_h ; ad_ likewise
__global__ void gat_scal_k(const float* __restrict__ h, const float* __restrict__ asrc,
                           const float* __restrict__ adst, float* as_, float* ad_,
                           int n, int H, int C){
    int idx = blockIdx.x*blockDim.x + threadIdx.x;
    if (idx >= n*H) return;
    int node = idx / H, hh = idx % H;
    const float* hp = h + (size_t)node*H*C + (size_t)hh*C;
    const float* ap = asrc + hh*C;
    const float* bp = adst + hh*C;
    float s=0.f, d=0.f;
#pragma unroll 8
    for (int c=0;c<C;c++){ float v=hp[c]; s += v*ap[c]; d += v*bp[c]; }
    as_[idx]=s; ad_[idx]=d;
}

// GAT1: H=4, C=64. warp per node; lane owns float4 channels [lane*4) (head lane>>4)
// and [128+lane*4) (head 2+(lane>>4)). online softmax (2 passes), fused bias+elu.
__global__ void gat1_gather_k(const float4* __restrict__ h4, const float4* __restrict__ as4,
                              const float4* __restrict__ ad4,
                              const int* __restrict__ rp, const int* __restrict__ ci,
                              const float4* __restrict__ bias4, float4* __restrict__ out4, int n)
{
    int w = (blockIdx.x*blockDim.x + threadIdx.x) >> 5;
    if (w >= n) return;
    int lane = threadIdx.x & 31;
    bool lo = (lane < 16);
    int beg = rp[w], end = rp[w+1];
    float4 ad = ad4[w];
    float adv0 = lo ? ad.x : ad.y;
    float adv1 = lo ? ad.z : ad.w;
    float4 asw = as4[w];
    float es0 = lrelu((lo ? asw.x : asw.y) + adv0);
    float es1 = lrelu((lo ? asw.z : asw.w) + adv1);
    float m0 = es0, m1 = es1;
    for (int e = beg; e < end; e++){
        float4 a = as4[ci[e]];
        m0 = fmaxf(m0, lrelu((lo ? a.x : a.y) + adv0));
        m1 = fmaxf(m1, lrelu((lo ? a.z : a.w) + adv1));
    }
    float w0 = expf(es0 - m0), w1 = expf(es1 - m1);
    float den0 = w0, den1 = w1;
    float4 hv0 = h4[(size_t)w*64 + lane];
    float4 hv1 = h4[(size_t)w*64 + 32 + lane];
    float4 acc0 = make_float4(w0*hv0.x, w0*hv0.y, w0*hv0.z, w0*hv0.w);
    float4 acc1 = make_float4(w1*hv1.x, w1*hv1.y, w1*hv1.z, w1*hv1.w);
    for (int e = beg; e < end; e++){
        int s = ci[e];
        float4 a = as4[s];
        float we0 = expf(lrelu((lo ? a.x : a.y) + adv0) - m0);
        float we1 = expf(lrelu((lo ? a.z : a.w) + adv1) - m1);
        den0 += we0; den1 += we1;
        float4 v0 = h4[(size_t)s*64 + lane];
        float4 v1 = h4[(size_t)s*64 + 32 + lane];
        acc0.x += we0*v0.x; acc0.y += we0*v0.y; acc0.z += we0*v0.z; acc0.w += we0*v0.w;
        acc1.x += we1*v1.x; acc1.y += we1*v1.y; acc1.z += we1*v1.z; acc1.w += we1*v1.w;
    }
    float inv0 = 1.f/(den0 + 1e-16f), inv1 = 1.f/(den1 + 1e-16f);
    float4 b0 = bias4[lane], b1 = bias4[32+lane];
    float4 o0, o1;
    o0.x = elu(acc0.x*inv0 + b0.x); o0.y = elu(acc0.y*inv0 + b0.y);
    o0.z = elu(acc0.z*inv0 + b0.z); o0.w = elu(acc0.w*inv0 + b0.w);
    o1.x = elu(acc1.x*inv1 + b1.x); o1.y = elu(acc1.y*inv1 + b1.y);
    o1.z = elu(acc1.z*inv1 + b1.z); o1.w = elu(acc1.w*inv1 + b1.w);
    out4[(size_t)w*64 + lane] = o0;
    out4[(size_t)w*64 + 32 + lane] = o1;
}

// GAT2: H=1, C=64. warp per node, lane owns channels {lane, lane+32}.
__global__ void gat2_gather_k(const float* __restrict__ h, const float* __restrict__ as_,
                              const float* __restrict__ ad_,
                              const int* __restrict__ rp, const int* __restrict__ ci,
                              const float* __restrict__ bias, float* __restrict__ out, int n)
{
    int w = (blockIdx.x*blockDim.x + threadIdx.x) >> 5;
    if (w >= n) return;
    int lane = threadIdx.x & 31;
    int beg = rp[w], end = rp[w+1];
    float adv = ad_[w];
    float es = lrelu(as_[w] + adv);
    float m = es;
    for (int e = beg; e < end; e++)
        m = fmaxf(m, lrelu(as_[ci[e]] + adv));
    float w0 = expf(es - m);
    float den = w0;
    float a0 = w0 * h[(size_t)w*64 + lane];
    float a1 = w0 * h[(size_t)w*64 + 32 + lane];
    for (int e = beg; e < end; e++){
        int s = ci[e];
        float we = expf(lrelu(as_[s] + adv) - m);
        den += we;
        a0 += we * h[(size_t)s*64 + lane];
        a1 += we * h[(size_t)s*64 + 32 + lane];
    }
    float inv = 1.f/(den + 1e-16f);
    float r0 = a0*inv + bias[lane];
    float r1 = a1*inv + bias[32+lane];
    out[(size_t)w*64 + lane]      = elu(r0);
    out[(size_t)w*64 + 32 + lane] = elu(r1);
}

// ---------------- BatchNorm ----------------
__global__ void fill_k(float* p, float v, int n){
    int i = blockIdx.x*blockDim.x + threadIdx.x;
    if (i < n) p[i] = v;
}
__global__ void bn_stats_k(const float* __restrict__ x, float* gsum, float* gsq, int total){
    __shared__ float ss[256];
    __shared__ float sq[256];
    int tid = threadIdx.x;
    float s = 0.f, q = 0.f;
    for (int i = blockIdx.x*256 + tid; i < total; i += gridDim.x*256){
        float v = x[i];
        s += v; q += v*v;
    }
    ss[tid] = s; sq[tid] = q;
    __syncthreads();
    if (tid < 64){
        int c = tid & 63;
        float ts = ss[tid] + ss[tid+64] + ss[tid+128] + ss[tid+192];
        float tq = sq[tid] + sq[tid+64] + sq[tid+128] + sq[tid+192];
        atomicAdd(&gsum[c], ts);
        atomicAdd(&gsq[c], tq);
    }
}
__global__ void bn_final_k(const float* gsum, const float* gsq, float* mean, float* var, int n){
    int c = threadIdx.x;
    if (c < 64){
        float m = gsum[c] / (float)n;
        mean[c] = m;
        var[c] = gsq[c] / (float)n - m*m;
    }
}
__global__ void bn_apply_k(const float* __restrict__ x, const float* __restrict__ mean,
                           const float* __restrict__ var, const float* __restrict__ g,
                           const float* __restrict__ b, float* cat, int n, int off){
    int i = blockIdx.x*blockDim.x + threadIdx.x;
    if (i >= n*64) return;
    int c = i & 63;
    float v = (x[i] - mean[c]) * rsqrtf(var[c] + 1e-5f) * g[c] + b[c];
    cat[(size_t)(i >> 6)*192 + off + c] = v;
}

// ---------------- fc2: [n,64] @ [64,2] + b ----------------
__global__ void fc2_k(const float* __restrict__ in, const float* __restrict__ w,
                      const float* __restrict__ b, float* __restrict__ out, int n){
    __shared__ float ws[128];
    if (threadIdx.x < 128) ws[threadIdx.x] = w[threadIdx.x];
    __syncthreads();
    int i = blockIdx.x*blockDim.x + threadIdx.x;
    if (i >= n) return;
    const float4* r = (const float4*)(in + (size_t)i*64);
    float s0 = 0.f, s1 = 0.f;
#pragma unroll
    for (int k=0;k<16;k++){
        float4 v = r[k];
        s0 += v.x*ws[(k*4+0)*2] + v.y*ws[(k*4+1)*2] + v.z*ws[(k*4+2)*2] + v.w*ws[(k*4+3)*2];
        s1 += v.x*ws[(k*4+0)*2+1] + v.y*ws[(k*4+1)*2+1] + v.z*ws[(k*4+2)*2+1] + v.w*ws[(k*4+3)*2+1];
    }
    out[(size_t)i*2]   = s0 + b[0];
    out[(size_t)i*2+1] = s1 + b[1];
}

// ---------------- host orchestration ----------------
static inline float* symf(const void* s){ void* p=nullptr; cudaGetSymbolAddress(&p, s); return (float*)p; }
static inline int*   symi(const void* s){ void* p=nullptr; cudaGetSymbolAddress(&p, s); return (int*)p; }

extern "C" void kernel_launch(void* const* d_in, const int* in_sizes, int n_in,
                              void* d_out, int out_size)
{
    const float* x        = (const float*)d_in[0];
    const int*   eidx     = (const int*)  d_in[1];
    const float* gcn1_w   = (const float*)d_in[2];
    const float* gcn1_b   = (const float*)d_in[3];
    const float* gcn2_w   = (const float*)d_in[4];
    const float* gcn2_b   = (const float*)d_in[5];
    const float* gat1_w   = (const float*)d_in[6];
    const float* gat1_as  = (const float*)d_in[7];
    const float* gat1_ad  = (const float*)d_in[8];
    const float* gat1_b   = (const float*)d_in[9];
    const float* gat2_w   = (const float*)d_in[10];
    const float* gat2_as  = (const float*)d_in[11];
    const float* gat2_ad  = (const float*)d_in[12];
    const float* gat2_b   = (const float*)d_in[13];
    const float* sage1_wl = (const float*)d_in[14];
    const float* sage1_bl = (const float*)d_in[15];
    const float* sage1_wr = (const float*)d_in[16];
    const float* sage2_wl = (const float*)d_in[17];
    const float* sage2_bl = (const float*)d_in[18];
    const float* sage2_wr = (const float*)d_in[19];
    const float* bng_g    = (const float*)d_in[20];
    const float* bng_b    = (const float*)d_in[21];
    const float* bna_g    = (const float*)d_in[22];
    const float* bna_b    = (const float*)d_in[23];
    const float* bns_g    = (const float*)d_in[24];
    const float* bns_b    = (const float*)d_in[25];
    const float* fc1_w    = (const float*)d_in[26];
    const float* fc1_b    = (const float*)d_in[27];
    const float* fc2_w    = (const float*)d_in[28];
    const float* fc2_b    = (const float*)d_in[29];
    float* out = (float*)d_out;

    const int n = in_sizes[0] / 128;
    const int E = in_sizes[1] / 2;
    const int* src = eidx;
    const int* dst = eidx + E;

    float* h    = symf(d_h);
    float* g1   = symf(d_g1);
    float* g2   = symf(d_g2);
    float* a1   = symf(d_a1);
    float* a2   = symf(d_a2);
    float* s1   = symf(d_s1);
    float* s2   = symf(d_s2);
    float* hl   = symf(d_hl);
    float* cat  = symf(d_cat);
    float* fc1o = symf(d_fc1o);
    float* as_  = symf(d_as);
    float* ad_  = symf(d_ad);
    float* dinv = symf(d_dinv);
    int*   cnt  = symi(d_cnt);
    int*   rp   = symi(d_rp);
    int*   cur  = symi(d_cur);
    int*   ci   = symi(d_ci);
    float* bsum = symf(d_bnsum);
    float* bsq  = symf(d_bnsq);
    float* bmean= symf(d_bnmean);
    float* bvar = symf(d_bnvar);

    const int T = 256;
    auto B  = [](int cnt_){ return dim3(CDIV(cnt_, 256)); };
    auto BW = [n](){ return dim3(CDIV(n*32, 256)); };  // warp-per-node grids

    // ---- CSR build (by dst) ----
    izero_k<<<B(n), T>>>(cnt, n);
    hist_k<<<B(E), T>>>(dst, cnt, E);
    scan_k<<<1, 1024>>>(cnt, rp, n);
    icopy_k<<<B(n), T>>>(rp, cur, n);
    csr_fill_k<<<B(E), T>>>(src, dst, cur, ci, E);
    dinv_k<<<B(n), T>>>(cnt, dinv, n);

    // ---- GCN ----
    gemm128_k<<<dim3(CDIV(n,128),1), T>>>(x, gcn1_w, h, nullptr, n, 128, 64, 0);
    gcn_gather_k<<<BW(), T>>>(h, dinv, rp, ci, gcn1_b, g1, n);
    gemm128_k<<<dim3(CDIV(n,128),1), T>>>(g1, gcn2_w, h, nullptr, n, 64, 64, 0);
    gcn_gather_k<<<BW(), T>>>(h, dinv, rp, ci, gcn2_b, g2, n);
    fill_k<<<1, 64>>>(bsum, 0.f, 64);
    fill_k<<<1, 64>>>(bsq, 0.f, 64);
    bn_stats_k<<<256, T>>>(g2, bsum, bsq, n*64);
    bn_final_k<<<1, 64>>>(bsum, bsq, bmean, bvar, n);
    bn_apply_k<<<B(n*64), T>>>(g2, bmean, bvar, bng_g, bng_b, cat, n, 0);

    // ---- GAT layer 1 (4 heads x 64, concat) ----
    gemm128_k<<<dim3(CDIV(n,128),4), T>>>(x, gat1_w, h, nullptr, n, 128, 256, 0);
    gat_scal_k<<<B(n*4), T>>>(h, gat1_as, gat1_ad, as_, ad_, n, 4, 64);
    gat1_gather_k<<<BW(), T>>>((const float4*)h, (const float4*)as_, (const float4*)ad_,
                               rp, ci, (const float4*)gat1_b, (float4*)a1, n);
    // ---- GAT layer 2 (1 head x 64, mean==identity) ----
    gemm128_k<<<dim3(CDIV(n,128),1), T>>>(a1, gat2_w, h, nullptr, n, 256, 64, 0);
    gat_scal_k<<<B(n), T>>>(h, gat2_as, gat2_ad, as_, ad_, n, 1, 64);
    gat2_gather_k<<<BW(), T>>>(h, as_, ad_, rp, ci, gat2_b, a2, n);
    fill_k<<<1, 64>>>(bsum, 0.f, 64);
    fill_k<<<1, 64>>>(bsq, 0.f, 64);
    bn_stats_k<<<256, T>>>(a2, bsum, bsq, n*64);
    bn_final_k<<<1, 64>>>(bsum, bsq, bmean, bvar, n);
    bn_apply_k<<<B(n*64), T>>>(a2, bmean, bvar, bna_g, bna_b, cat, n, 64);

    // ---- SAGE (linear commutes with mean: aggregate x@Wl instead of x) ----
    gemm128_k<<<dim3(CDIV(n,128),1), T>>>(x, sage1_wl, hl, nullptr, n, 128, 64, 0);
    gemm128_k<<<dim3(CDIV(n,128),1), T>>>(x, sage1_wr, h,  nullptr, n, 128, 64, 0);
    sage_gather_k<<<BW(), T>>>(hl, h, rp, ci, sage1_bl, s1, n);
    gemm128_k<<<dim3(CDIV(n,128),1), T>>>(s1, sage2_wl, hl, nullptr, n, 64, 64, 0);
    gemm128_k<<<dim3(CDIV(n,128),1), T>>>(s1, sage2_wr, h,  nullptr, n, 64, 64, 0);
    sage_gather_k<<<BW(), T>>>(hl, h, rp, ci, sage2_bl, s2, n);
    fill_k<<<1, 64>>>(bsum, 0.f, 64);
    fill_k<<<1, 64>>>(bsq, 0.f, 64);
    bn_stats_k<<<256, T>>>(s2, bsum, bsq, n*64);
    bn_final_k<<<1, 64>>>(bsum, bsq, bmean, bvar, n);
    bn_apply_k<<<B(n*64), T>>>(s2, bmean, bvar, bns_g, bns_b, cat, n, 128);

    // ---- MLP head ----
    gemm128_k<<<dim3(CDIV(n,128),1), T>>>(cat, fc1_w, fc1o, fc1_b, n, 192, 64, 1);
    fc2_k<<<B(n), T>>>(fc1o, fc2_w, fc2_b, out, n);
}

// round 7
// speedup vs baseline: 3.2423x; 1.2040x over previous
#include <cuda_runtime.h>
#include <cstdint>
#include <cstdio>

#define NMAX 50000
#define EMAX 600000
#define CDIV(a,b) (((a)+(b)-1)/(b))

// ---------------- scratch (device globals; no allocation allowed) ----------------
__device__ __align__(16) float d_h   [(size_t)NMAX*256];
__device__ __align__(16) float d_g1  [(size_t)NMAX*64];
__device__ __align__(16) float d_g2  [(size_t)NMAX*64];
__device__ __align__(16) float d_a1  [(size_t)NMAX*256];
__device__ __align__(16) float d_a2  [(size_t)NMAX*64];
__device__ __align__(16) float d_s1  [(size_t)NMAX*64];
__device__ __align__(16) float d_s2  [(size_t)NMAX*64];
__device__ __align__(16) float d_hl  [(size_t)NMAX*64];
__device__ __align__(16) float d_cat [(size_t)NMAX*192];
__device__ __align__(16) float d_fc1o[(size_t)NMAX*64];
__device__ __align__(16) float d_as  [(size_t)NMAX*4];
__device__ __align__(16) float d_ad  [(size_t)NMAX*4];
__device__ float d_dinv[NMAX];
__device__ int   d_cnt [NMAX];
__device__ int   d_rp  [NMAX+1];
__device__ int   d_cur [NMAX];
__device__ int   d_ci  [EMAX];
__device__ float d_bnsum[64];   // zero-init at load; bn_final re-zeroes after use
__device__ float d_bnsq [64];
__device__ float d_bnmean[64];
__device__ float d_bnvar [64];

// ---------------- helpers ----------------
__device__ __forceinline__ float lrelu(float x){ return x > 0.f ? x : 0.2f * x; }
__device__ __forceinline__ float elu(float x){ return x > 0.f ? x : expm1f(x); }

__device__ __forceinline__ uint32_t f2tf32(float f){
    uint32_t u;
    asm("cvt.rna.tf32.f32 %0, %1;" : "=r"(u) : "f"(f));
    return u;
}
__device__ __forceinline__ void mma_tf32(float4& d,
    uint32_t a0, uint32_t a1, uint32_t a2, uint32_t a3,
    uint32_t b0, uint32_t b1)
{
    asm volatile(
        "mma.sync.aligned.m16n8k8.row.col.f32.tf32.tf32.f32 "
        "{%0,%1,%2,%3}, {%4,%5,%6,%7}, {%8,%9}, {%0,%1,%2,%3};"
        : "+f"(d.x), "+f"(d.y), "+f"(d.z), "+f"(d.w)
        : "r"(a0), "r"(a1), "r"(a2), "r"(a3), "r"(b0), "r"(b1));
}

// ---------------- CSR build ----------------
__global__ void izero_k(int* p, int n){
    int i = blockIdx.x*blockDim.x + threadIdx.x;
    if (i < n) p[i] = 0;
}
__global__ void hist_k(const int* __restrict__ dst, int* cnt, int E){
    int i = blockIdx.x*blockDim.x + threadIdx.x;
    if (i < E) atomicAdd(&cnt[dst[i]], 1);
}
// single-block scan: rp[0]=0, rp[i+1]=incl sum; cur[i]=exclusive sum (cursor init)
__global__ void scan_k(const int* __restrict__ cnt, int* rp, int* cur, int n){
    __shared__ int wsum[32];
    __shared__ int carry_s;
    int lane = threadIdx.x & 31, wid = threadIdx.x >> 5;
    if (threadIdx.x == 0){ carry_s = 0; rp[0] = 0; }
    __syncthreads();
    for (int base = 0; base < n; base += 1024){
        int i = base + threadIdx.x;
        int v = (i < n) ? cnt[i] : 0;
        int x = v;
#pragma unroll
        for (int o = 1; o < 32; o <<= 1){
            int t = __shfl_up_sync(0xffffffffu, x, o);
            if (lane >= o) x += t;
        }
        if (lane == 31) wsum[wid] = x;
        __syncthreads();
        if (wid == 0){
            int y = wsum[lane];
#pragma unroll
            for (int o = 1; o < 32; o <<= 1){
                int t = __shfl_up_sync(0xffffffffu, y, o);
                if (lane >= o) y += t;
            }
            wsum[lane] = y;
        }
        __syncthreads();
        int incl = x + (wid > 0 ? wsum[wid-1] : 0) + carry_s;
        if (i < n){ rp[i+1] = incl; cur[i] = incl - v; }
        __syncthreads();
        if (threadIdx.x == 1023) carry_s = incl;
        __syncthreads();
    }
}
__global__ void csr_fill_k(const int* __restrict__ src, const int* __restrict__ dst,
                           int* cursor, int* ci, int E){
    int e = blockIdx.x*blockDim.x + threadIdx.x;
    if (e < E){
        int p = atomicAdd(&cursor[dst[e]], 1);
        ci[p] = src[e];
    }
}
__global__ void dinv_k(const int* __restrict__ cnt, float* dinv, int n){
    int i = blockIdx.x*blockDim.x + threadIdx.x;
    if (i < n) dinv[i] = rsqrtf((float)cnt[i] + 1.0f);  // +1 self-loop
}

// ---------------- tf32 tensor-core GEMM ----------------
// C[M,F] = A[M,K] @ B[K,F] (+bias)(+relu); K%32==0, F%64==0
// block 128x64, 8 warps (4x2), warp tile 32x32 of m16n8k8 mma.
__global__ __launch_bounds__(256) void gemm_mma_k(
    const float* __restrict__ A, const float* __restrict__ B,
    float* __restrict__ C, const float* __restrict__ bias,
    int M, int K, int F, int act)
{
    __shared__ uint32_t As[32][136];  // [k][m], stride%32==8 -> conflict-free frags
    __shared__ uint32_t Bs[32][72];   // [k][n], stride%32==8
    int bm = blockIdx.x * 128;
    int bn = blockIdx.y * 64;
    int tid = threadIdx.x;
    int w = tid >> 5, lane = tid & 31;
    int wm = w & 3, wn = w >> 2;          // warp grid 4(M) x 2(N)
    int g = lane >> 2, ti = lane & 3;     // group / thread-in-group

    float4 acc[2][4];
#pragma unroll
    for (int i=0;i<2;i++)
#pragma unroll
        for (int j=0;j<4;j++) acc[i][j] = make_float4(0.f,0.f,0.f,0.f);

    for (int k0 = 0; k0 < K; k0 += 32){
        // A tile 128x32 -> As[k][m] (tf32)
#pragma unroll
        for (int i=0;i<4;i++){
            int l = tid*4 + i;
            int m = l >> 3, kq = l & 7;
            float4 v = make_float4(0.f,0.f,0.f,0.f);
            if (bm + m < M) v = *(const float4*)&A[(size_t)(bm+m)*K + k0 + kq*4];
            As[kq*4+0][m] = f2tf32(v.x);
            As[kq*4+1][m] = f2tf32(v.y);
            As[kq*4+2][m] = f2tf32(v.z);
            As[kq*4+3][m] = f2tf32(v.w);
        }
        // B tile 32x64 -> Bs[k][n] (tf32)
#pragma unroll
        for (int i=0;i<2;i++){
            int l = tid*2 + i;
            int kk = l >> 4, nq = l & 15;
            float4 v = *(const float4*)&B[(size_t)(k0+kk)*F + bn + nq*4];
            Bs[kk][nq*4+0] = f2tf32(v.x);
            Bs[kk][nq*4+1] = f2tf32(v.y);
            Bs[kk][nq*4+2] = f2tf32(v.z);
            Bs[kk][nq*4+3] = f2tf32(v.w);
        }
        __syncthreads();
#pragma unroll
        for (int kk = 0; kk < 32; kk += 8){
            uint32_t bf[4][2];
#pragma unroll
            for (int j=0;j<4;j++){
                bf[j][0] = Bs[kk + ti    ][wn*32 + j*8 + g];
                bf[j][1] = Bs[kk + 4 + ti][wn*32 + j*8 + g];
            }
#pragma unroll
            for (int mi=0;mi<2;mi++){
                int mb = wm*32 + mi*16;
                uint32_t a0 = As[kk + ti    ][mb + g];
                uint32_t a1 = As[kk + ti    ][mb + g + 8];
                uint32_t a2 = As[kk + 4 + ti][mb + g];
                uint32_t a3 = As[kk + 4 + ti][mb + g + 8];
#pragma unroll
                for (int j=0;j<4;j++)
                    mma_tf32(acc[mi][j], a0, a1, a2, a3, bf[j][0], bf[j][1]);
            }
        }
        __syncthreads();
    }

    // epilogue: frag (mi,j): rows bm+wm*32+mi*16+{g, g+8}, cols bn+wn*32+j*8+2*ti+{0,1}
#pragma unroll
    for (int mi=0;mi<2;mi++){
#pragma unroll
        for (int j=0;j<4;j++){
            int c = bn + wn*32 + j*8 + 2*ti;
            float b0 = bias ? bias[c]   : 0.f;
            float b1 = bias ? bias[c+1] : 0.f;
            float4 a = acc[mi][j];
            float2 v0 = make_float2(a.x + b0, a.y + b1);
            float2 v1 = make_float2(a.z + b0, a.w + b1);
            if (act){
                v0.x = fmaxf(v0.x, 0.f); v0.y = fmaxf(v0.y, 0.f);
                v1.x = fmaxf(v1.x, 0.f); v1.y = fmaxf(v1.y, 0.f);
            }
            int r0 = bm + wm*32 + mi*16 + g;
            int r1 = r0 + 8;
            if (r0 < M) *(float2*)&C[(size_t)r0*F + c] = v0;
            if (r1 < M) *(float2*)&C[(size_t)r1*F + c] = v1;
        }
    }
}

// ---------------- fused gather kernels (warp per node) ----------------
__global__ void gcn_gather_k(const float* __restrict__ h, const float* __restrict__ dinv,
                             const int* __restrict__ rp, const int* __restrict__ ci,
                             const float* __restrict__ bias, float* __restrict__ out, int n)
{
    int w = (blockIdx.x*blockDim.x + threadIdx.x) >> 5;
    if (w >= n) return;
    int lane = threadIdx.x & 31;
    int beg = rp[w], end = rp[w+1];
    float dvd = dinv[w];
    float a0 = dvd * h[(size_t)w*64 + lane];
    float a1 = dvd * h[(size_t)w*64 + 32 + lane];
    for (int e = beg; e < end; e++){
        int s = ci[e];
        float ds = dinv[s];
        a0 += ds * h[(size_t)s*64 + lane];
        a1 += ds * h[(size_t)s*64 + 32 + lane];
    }
    out[(size_t)w*64 + lane]      = fmaxf(dvd*a0 + bias[lane],      0.f);
    out[(size_t)w*64 + 32 + lane] = fmaxf(dvd*a1 + bias[32+lane],   0.f);
}

__global__ void sage_gather_k(const float* __restrict__ hl, const float* __restrict__ xr,
                              const int* __restrict__ rp, const int* __restrict__ ci,
                              const float* __restrict__ bl, float* __restrict__ out, int n)
{
    int w = (blockIdx.x*blockDim.x + threadIdx.x) >> 5;
    if (w >= n) return;
    int lane = threadIdx.x & 31;
    int beg = rp[w], end = rp[w+1];
    float a0 = 0.f, a1 = 0.f;
    for (int e = beg; e < end; e++){
        int s = ci[e];
        a0 += hl[(size_t)s*64 + lane];
        a1 += hl[(size_t)s*64 + 32 + lane];
    }
    float inv = 1.f / fmaxf((float)(end - beg), 1.f);
    out[(size_t)w*64 + lane]      = fmaxf(a0*inv + bl[lane]    + xr[(size_t)w*64 + lane],      0.f);
    out[(size_t)w*64 + 32 + lane] = fmaxf(a1*inv + bl[32+lane] + xr[(size_t)w*64 + 32 + lane], 0.f);
}

__global__ void gat_scal_k(const float* __restrict__ h, const float* __restrict__ asrc,
                           const float* __restrict__ adst, float* as_, float* ad_,
                           int n, int H, int C){
    int idx = blockIdx.x*blockDim.x + threadIdx.x;
    if (idx >= n*H) return;
    int node = idx / H, hh = idx % H;
    const float* hp = h + (size_t)node*H*C + (size_t)hh*C;
    const float* ap = asrc + hh*C;
    const float* bp = adst + hh*C;
    float s=0.f, d=0.f;
#pragma unroll 8
    for (int c=0;c<C;c++){ float v=hp[c]; s += v*ap[c]; d += v*bp[c]; }
    as_[idx]=s; ad_[idx]=d;
}

__global__ void gat1_gather_k(const float4* __restrict__ h4, const float4* __restrict__ as4,
                              const float4* __restrict__ ad4,
                              const int* __restrict__ rp, const int* __restrict__ ci,
                              const float4* __restrict__ bias4, float4* __restrict__ out4, int n)
{
    int w = (blockIdx.x*blockDim.x + threadIdx.x) >> 5;
    if (w >= n) return;
    int lane = threadIdx.x & 31;
    bool lo = (lane < 16);
    int beg = rp[w], end = rp[w+1];
    float4 ad = ad4[w];
    float adv0 = lo ? ad.x : ad.y;
    float adv1 = lo ? ad.z : ad.w;
    float4 asw = as4[w];
    float es0 = lrelu((lo ? asw.x : asw.y) + adv0);
    float es1 = lrelu((lo ? asw.z : asw.w) + adv1);
    float m0 = es0, m1 = es1;
    for (int e = beg; e < end; e++){
        float4 a = as4[ci[e]];
        m0 = fmaxf(m0, lrelu((lo ? a.x : a.y) + adv0));
        m1 = fmaxf(m1, lrelu((lo ? a.z : a.w) + adv1));
    }
    float w0 = expf(es0 - m0), w1 = expf(es1 - m1);
    float den0 = w0, den1 = w1;
    float4 hv0 = h4[(size_t)w*64 + lane];
    float4 hv1 = h4[(size_t)w*64 + 32 + lane];
    float4 acc0 = make_float4(w0*hv0.x, w0*hv0.y, w0*hv0.z, w0*hv0.w);
    float4 acc1 = make_float4(w1*hv1.x, w1*hv1.y, w1*hv1.z, w1*hv1.w);
    for (int e = beg; e < end; e++){
        int s = ci[e];
        float4 a = as4[s];
        float we0 = expf(lrelu((lo ? a.x : a.y) + adv0) - m0);
        float we1 = expf(lrelu((lo ? a.z : a.w) + adv1) - m1);
        den0 += we0; den1 += we1;
        float4 v0 = h4[(size_t)s*64 + lane];
        float4 v1 = h4[(size_t)s*64 + 32 + lane];
        acc0.x += we0*v0.x; acc0.y += we0*v0.y; acc0.z += we0*v0.z; acc0.w += we0*v0.w;
        acc1.x += we1*v1.x; acc1.y += we1*v1.y; acc1.z += we1*v1.z; acc1.w += we1*v1.w;
    }
    float inv0 = 1.f/(den0 + 1e-16f), inv1 = 1.f/(den1 + 1e-16f);
    float4 b0 = bias4[lane], b1 = bias4[32+lane];
    float4 o0, o1;
    o0.x = elu(acc0.x*inv0 + b0.x); o0.y = elu(acc0.y*inv0 + b0.y);
    o0.z = elu(acc0.z*inv0 + b0.z); o0.w = elu(acc0.w*inv0 + b0.w);
    o1.x = elu(acc1.x*inv1 + b1.x); o1.y = elu(acc1.y*inv1 + b1.y);
    o1.z = elu(acc1.z*inv1 + b1.z); o1.w = elu(acc1.w*inv1 + b1.w);
    out4[(size_t)w*64 + lane] = o0;
    out4[(size_t)w*64 + 32 + lane] = o1;
}

__global__ void gat2_gather_k(const float* __restrict__ h, const float* __restrict__ as_,
                              const float* __restrict__ ad_,
                              const int* __restrict__ rp, const int* __restrict__ ci,
                              const float* __restrict__ bias, float* __restrict__ out, int n)
{
    int w = (blockIdx.x*blockDim.x + threadIdx.x) >> 5;
    if (w >= n) return;
    int lane = threadIdx.x & 31;
    int beg = rp[w], end = rp[w+1];
    float adv = ad_[w];
    float es = lrelu(as_[w] + adv);
    float m = es;
    for (int e = beg; e < end; e++)
        m = fmaxf(m, lrelu(as_[ci[e]] + adv));
    float w0 = expf(es - m);
    float den = w0;
    float a0 = w0 * h[(size_t)w*64 + lane];
    float a1 = w0 * h[(size_t)w*64 + 32 + lane];
    for (int e = beg; e < end; e++){
        int s = ci[e];
        float we = expf(lrelu(as_[s] + adv) - m);
        den += we;
        a0 += we * h[(size_t)s*64 + lane];
        a1 += we * h[(size_t)s*64 + 32 + lane];
    }
    float inv = 1.f/(den + 1e-16f);
    out[(size_t)w*64 + lane]      = elu(a0*inv + bias[lane]);
    out[(size_t)w*64 + 32 + lane] = elu(a1*inv + bias[32+lane]);
}

// ---------------- BatchNorm ----------------
__global__ void bn_stats_k(const float* __restrict__ x, float* gsum, float* gsq, int total){
    __shared__ float ss[256];
    __shared__ float sq[256];
    int tid = threadIdx.x;
    float s = 0.f, q = 0.f;
    for (int i = blockIdx.x*256 + tid; i < total; i += gridDim.x*256){
        float v = x[i];
        s += v; q += v*v;
    }
    ss[tid] = s; sq[tid] = q;
    __syncthreads();
    if (tid < 64){
        int c = tid & 63;
        float ts = ss[tid] + ss[tid+64] + ss[tid+128] + ss[tid+192];
        float tq = sq[tid] + sq[tid+64] + sq[tid+128] + sq[tid+192];
        atomicAdd(&gsum[c], ts);
        atomicAdd(&gsq[c], tq);
    }
}
// computes mean/var AND re-zeroes accumulators for the next use (deterministic
// across graph replays: every consumer restores the zero it consumed)
__global__ void bn_final_k(float* gsum, float* gsq, float* mean, float* var, int n){
    int c = threadIdx.x;
    if (c < 64){
        float m = gsum[c] / (float)n;
        mean[c] = m;
        var[c] = gsq[c] / (float)n - m*m;
        gsum[c] = 0.f;
        gsq[c]  = 0.f;
    }
}
__global__ void bn_apply_k(const float* __restrict__ x, const float* __restrict__ mean,
                           const float* __restrict__ var, const float* __restrict__ g,
                           const float* __restrict__ b, float* cat, int n, int off){
    int i = blockIdx.x*blockDim.x + threadIdx.x;
    if (i >= n*64) return;
    int c = i & 63;
    float v = (x[i] - mean[c]) * rsqrtf(var[c] + 1e-5f) * g[c] + b[c];
    cat[(size_t)(i >> 6)*192 + off + c] = v;
}

// ---------------- fc2: [n,64] @ [64,2] + b ----------------
__global__ void fc2_k(const float* __restrict__ in, const float* __restrict__ w,
                      const float* __restrict__ b, float* __restrict__ out, int n){
    __shared__ float ws[128];
    if (threadIdx.x < 128) ws[threadIdx.x] = w[threadIdx.x];
    __syncthreads();
    int i = blockIdx.x*blockDim.x + threadIdx.x;
    if (i >= n) return;
    const float4* r = (const float4*)(in + (size_t)i*64);
    float s0 = 0.f, s1 = 0.f;
#pragma unroll
    for (int k=0;k<16;k++){
        float4 v = r[k];
        s0 += v.x*ws[(k*4+0)*2] + v.y*ws[(k*4+1)*2] + v.z*ws[(k*4+2)*2] + v.w*ws[(k*4+3)*2];
        s1 += v.x*ws[(k*4+0)*2+1] + v.y*ws[(k*4+1)*2+1] + v.z*ws[(k*4+2)*2+1] + v.w*ws[(k*4+3)*2+1];
    }
    out[(size_t)i*2]   = s0 + b[0];
    out[(size_t)i*2+1] = s1 + b[1];
}

// ---------------- host orchestration ----------------
static inline float* symf(const void* s){ void* p=nullptr; cudaGetSymbolAddress(&p, s); return (float*)p; }
static inline int*   symi(const void* s){ void* p=nullptr; cudaGetSymbolAddress(&p, s); return (int*)p; }

extern "C" void kernel_launch(void* const* d_in, const int* in_sizes, int n_in,
                              void* d_out, int out_size)
{
    const float* x        = (const float*)d_in[0];
    const int*   eidx     = (const int*)  d_in[1];
    const float* gcn1_w   = (const float*)d_in[2];
    const float* gcn1_b   = (const float*)d_in[3];
    const float* gcn2_w   = (const float*)d_in[4];
    const float* gcn2_b   = (const float*)d_in[5];
    const float* gat1_w   = (const float*)d_in[6];
    const float* gat1_as  = (const float*)d_in[7];
    const float* gat1_ad  = (const float*)d_in[8];
    const float* gat1_b   = (const float*)d_in[9];
    const float* gat2_w   = (const float*)d_in[10];
    const float* gat2_as  = (const float*)d_in[11];
    const float* gat2_ad  = (const float*)d_in[12];
    const float* gat2_b   = (const float*)d_in[13];
    const float* sage1_wl = (const float*)d_in[14];
    const float* sage1_bl = (const float*)d_in[15];
    const float* sage1_wr = (const float*)d_in[16];
    const float* sage2_wl = (const float*)d_in[17];
    const float* sage2_bl = (const float*)d_in[18];
    const float* sage2_wr = (const float*)d_in[19];
    const float* bng_g    = (const float*)d_in[20];
    const float* bng_b    = (const float*)d_in[21];
    const float* bna_g    = (const float*)d_in[22];
    const float* bna_b    = (const float*)d_in[23];
    const float* bns_g    = (const float*)d_in[24];
    const float* bns_b    = (const float*)d_in[25];
    const float* fc1_w    = (const float*)d_in[26];
    const float* fc1_b    = (const float*)d_in[27];
    const float* fc2_w    = (const float*)d_in[28];
    const float* fc2_b    = (const float*)d_in[29];
    float* out = (float*)d_out;

    const int n = in_sizes[0] / 128;
    const int E = in_sizes[1] / 2;
    const int* src = eidx;
    const int* dst = eidx + E;

    float* h    = symf(d_h);
    float* g1   = symf(d_g1);
    float* g2   = symf(d_g2);
    float* a1   = symf(d_a1);
    float* a2   = symf(d_a2);
    float* s1   = symf(d_s1);
    float* s2   = symf(d_s2);
    float* hl   = symf(d_hl);
    float* cat  = symf(d_cat);
    float* fc1o = symf(d_fc1o);
    float* as_  = symf(d_as);
    float* ad_  = symf(d_ad);
    float* dinv = symf(d_dinv);
    int*   cnt  = symi(d_cnt);
    int*   rp   = symi(d_rp);
    int*   cur  = symi(d_cur);
    int*   ci   = symi(d_ci);
    float* bsum = symf(d_bnsum);
    float* bsq  = symf(d_bnsq);
    float* bmean= symf(d_bnmean);
    float* bvar = symf(d_bnvar);

    const int T = 256;
    auto B  = [](int cnt_){ return dim3(CDIV(cnt_, 256)); };
    auto BW = [n](){ return dim3(CDIV(n*32, 256)); };  // warp-per-node grids
    auto GG = [n](int F){ return dim3(CDIV(n,128), F/64); };

    // ---- CSR build (by dst) ----
    izero_k<<<B(n), T>>>(cnt, n);
    hist_k<<<B(E), T>>>(dst, cnt, E);
    scan_k<<<1, 1024>>>(cnt, rp, cur, n);
    csr_fill_k<<<B(E), T>>>(src, dst, cur, ci, E);
    dinv_k<<<B(n), T>>>(cnt, dinv, n);

    // ---- GCN ----
    gemm_mma_k<<<GG(64), T>>>(x, gcn1_w, h, nullptr, n, 128, 64, 0);
    gcn_gather_k<<<BW(), T>>>(h, dinv, rp, ci, gcn1_b, g1, n);
    gemm_mma_k<<<GG(64), T>>>(g1, gcn2_w, h, nullptr, n, 64, 64, 0);
    gcn_gather_k<<<BW(), T>>>(h, dinv, rp, ci, gcn2_b, g2, n);
    bn_stats_k<<<256, T>>>(g2, bsum, bsq, n*64);
    bn_final_k<<<1, 64>>>(bsum, bsq, bmean, bvar, n);
    bn_apply_k<<<B(n*64), T>>>(g2, bmean, bvar, bng_g, bng_b, cat, n, 0);

    // ---- GAT layer 1 (4 heads x 64, concat) ----
    gemm_mma_k<<<GG(256), T>>>(x, gat1_w, h, nullptr, n, 128, 256, 0);
    gat_scal_k<<<B(n*4), T>>>(h, gat1_as, gat1_ad, as_, ad_, n, 4, 64);
    gat1_gather_k<<<BW(), T>>>((const float4*)h, (const float4*)as_, (const float4*)ad_,
                               rp, ci, (const float4*)gat1_b, (float4*)a1, n);
    // ---- GAT layer 2 (1 head x 64) ----
    gemm_mma_k<<<GG(64), T>>>(a1, gat2_w, h, nullptr, n, 256, 64, 0);
    gat_scal_k<<<B(n), T>>>(h, gat2_as, gat2_ad, as_, ad_, n, 1, 64);
    gat2_gather_k<<<BW(), T>>>(h, as_, ad_, rp, ci, gat2_b, a2, n);
    bn_stats_k<<<256, T>>>(a2, bsum, bsq, n*64);
    bn_final_k<<<1, 64>>>(bsum, bsq, bmean, bvar, n);
    bn_apply_k<<<B(n*64), T>>>(a2, bmean, bvar, bna_g, bna_b, cat, n, 64);

    // ---- SAGE (linear commutes with mean: aggregate x@Wl instead of x) ----
    gemm_mma_k<<<GG(64), T>>>(x, sage1_wl, hl, nullptr, n, 128, 64, 0);
    gemm_mma_k<<<GG(64), T>>>(x, sage1_wr, h,  nullptr, n, 128, 64, 0);
    sage_gather_k<<<BW(), T>>>(hl, h, rp, ci, sage1_bl, s1, n);
    gemm_mma_k<<<GG(64), T>>>(s1, sage2_wl, hl, nullptr, n, 64, 64, 0);
    gemm_mma_k<<<GG(64), T>>>(s1, sage2_wr, h,  nullptr, n, 64, 64, 0);
    sage_gather_k<<<BW(), T>>>(hl, h, rp, ci, sage2_bl, s2, n);
    bn_stats_k<<<256, T>>>(s2, bsum, bsq, n*64);
    bn_final_k<<<1, 64>>>(bsum, bsq, bmean, bvar, n);
    bn_apply_k<<<B(n*64), T>>>(s2, bmean, bvar, bns_g, bns_b, cat, n, 128);

    // ---- MLP head ----
    gemm_mma_k<<<GG(64), T>>>(cat, fc1_w, fc1o, fc1_b, n, 192, 64, 1);
    fc2_k<<<B(n), T>>>(fc1o, fc2_w, fc2_b, out, n);
}

// round 8
// speedup vs baseline: 4.1033x; 1.2656x over previous
#include <cuda_runtime.h>
#include <cstdint>
#include <cstdio>

#define NMAX 50000
#define EMAX 600000
#define CDIV(a,b) (((a)+(b)-1)/(b))

// ---------------- scratch (device globals; no allocation allowed) ----------------
// per-branch buffers so the three GNN branches can run on concurrent streams
__device__ __align__(16) float d_hg  [(size_t)NMAX*64];   // GCN gemm out
__device__ __align__(16) float d_g1  [(size_t)NMAX*64];
__device__ __align__(16) float d_g2  [(size_t)NMAX*64];
__device__ __align__(16) float d_hgat[(size_t)NMAX*256];  // GAT gemm out
__device__ __align__(16) float d_a1  [(size_t)NMAX*256];
__device__ __align__(16) float d_a2  [(size_t)NMAX*64];
__device__ __align__(16) float d_hsl [(size_t)NMAX*64];   // SAGE x@Wl
__device__ __align__(16) float d_hsr [(size_t)NMAX*64];   // SAGE x@Wr
__device__ __align__(16) float d_s1  [(size_t)NMAX*64];
__device__ __align__(16) float d_s2  [(size_t)NMAX*64];
__device__ __align__(16) float d_cat [(size_t)NMAX*192];
__device__ __align__(16) float d_fc1o[(size_t)NMAX*64];
__device__ __align__(16) float d_as  [(size_t)NMAX*4];
__device__ __align__(16) float d_ad  [(size_t)NMAX*4];
__device__ float d_dinv[NMAX];
__device__ int   d_cnt [NMAX];
__device__ int   d_rp  [NMAX+1];
__device__ int   d_cur [NMAX];
__device__ int   d_ci  [EMAX];
__device__ float d_bnsum[192];   // 3 branches x 64; zero-init, bn_final re-zeroes
__device__ float d_bnsq [192];
__device__ float d_bnmean[192];
__device__ float d_bnvar [192];

// ---------------- helpers ----------------
__device__ __forceinline__ float lrelu(float x){ return x > 0.f ? x : 0.2f * x; }
__device__ __forceinline__ float elu(float x){ return x > 0.f ? x : expm1f(x); }

__device__ __forceinline__ uint32_t f2tf32(float f){
    uint32_t u;
    asm("cvt.rna.tf32.f32 %0, %1;" : "=r"(u) : "f"(f));
    return u;
}
__device__ __forceinline__ void mma_tf32(float4& d,
    uint32_t a0, uint32_t a1, uint32_t a2, uint32_t a3,
    uint32_t b0, uint32_t b1)
{
    asm volatile(
        "mma.sync.aligned.m16n8k8.row.col.f32.tf32.tf32.f32 "
        "{%0,%1,%2,%3}, {%4,%5,%6,%7}, {%8,%9}, {%0,%1,%2,%3};"
        : "+f"(d.x), "+f"(d.y), "+f"(d.z), "+f"(d.w)
        : "r"(a0), "r"(a1), "r"(a2), "r"(a3), "r"(b0), "r"(b1));
}

// ---------------- CSR build ----------------
__global__ void izero_k(int* p, int n){
    int i = blockIdx.x*blockDim.x + threadIdx.x;
    if (i < n) p[i] = 0;
}
__global__ void hist_k(const int* __restrict__ dst, int* cnt, int E){
    int i = blockIdx.x*blockDim.x + threadIdx.x;
    if (i < E) atomicAdd(&cnt[dst[i]], 1);
}
// single-block scan: rp[0]=0, rp[i+1]=incl sum; cur[i]=exclusive sum (cursor init)
__global__ void scan_k(const int* __restrict__ cnt, int* rp, int* cur, int n){
    __shared__ int wsum[32];
    __shared__ int carry_s;
    int lane = threadIdx.x & 31, wid = threadIdx.x >> 5;
    if (threadIdx.x == 0){ carry_s = 0; rp[0] = 0; }
    __syncthreads();
    for (int base = 0; base < n; base += 1024){
        int i = base + threadIdx.x;
        int v = (i < n) ? cnt[i] : 0;
        int x = v;
#pragma unroll
        for (int o = 1; o < 32; o <<= 1){
            int t = __shfl_up_sync(0xffffffffu, x, o);
            if (lane >= o) x += t;
        }
        if (lane == 31) wsum[wid] = x;
        __syncthreads();
        if (wid == 0){
            int y = wsum[lane];
#pragma unroll
            for (int o = 1; o < 32; o <<= 1){
                int t = __shfl_up_sync(0xffffffffu, y, o);
                if (lane >= o) y += t;
            }
            wsum[lane] = y;
        }
        __syncthreads();
        int incl = x + (wid > 0 ? wsum[wid-1] : 0) + carry_s;
        if (i < n){ rp[i+1] = incl; cur[i] = incl - v; }
        __syncthreads();
        if (threadIdx.x == 1023) carry_s = incl;
        __syncthreads();
    }
}
__global__ void csr_fill_k(const int* __restrict__ src, const int* __restrict__ dst,
                           int* cursor, int* ci, int E){
    int e = blockIdx.x*blockDim.x + threadIdx.x;
    if (e < E){
        int p = atomicAdd(&cursor[dst[e]], 1);
        ci[p] = src[e];
    }
}
__global__ void dinv_k(const int* __restrict__ cnt, float* dinv, int n){
    int i = blockIdx.x*blockDim.x + threadIdx.x;
    if (i < n) dinv[i] = rsqrtf((float)cnt[i] + 1.0f);  // +1 self-loop
}

// ---------------- tf32 tensor-core GEMM ----------------
// C[M,F] = A[M,K] @ B[K,F] (+bias)(+relu); K%32==0, F%64==0
__global__ __launch_bounds__(256) void gemm_mma_k(
    const float* __restrict__ A, const float* __restrict__ B,
    float* __restrict__ C, const float* __restrict__ bias,
    int M, int K, int F, int act)
{
    __shared__ uint32_t As[32][136];
    __shared__ uint32_t Bs[32][72];
    int bm = blockIdx.x * 128;
    int bn = blockIdx.y * 64;
    int tid = threadIdx.x;
    int w = tid >> 5, lane = tid & 31;
    int wm = w & 3, wn = w >> 2;
    int g = lane >> 2, ti = lane & 3;

    float4 acc[2][4];
#pragma unroll
    for (int i=0;i<2;i++)
#pragma unroll
        for (int j=0;j<4;j++) acc[i][j] = make_float4(0.f,0.f,0.f,0.f);

    for (int k0 = 0; k0 < K; k0 += 32){
#pragma unroll
        for (int i=0;i<4;i++){
            int l = tid*4 + i;
            int m = l >> 3, kq = l & 7;
            float4 v = make_float4(0.f,0.f,0.f,0.f);
            if (bm + m < M) v = *(const float4*)&A[(size_t)(bm+m)*K + k0 + kq*4];
            As[kq*4+0][m] = f2tf32(v.x);
            As[kq*4+1][m] = f2tf32(v.y);
            As[kq*4+2][m] = f2tf32(v.z);
            As[kq*4+3][m] = f2tf32(v.w);
        }
#pragma unroll
        for (int i=0;i<2;i++){
            int l = tid*2 + i;
            int kk = l >> 4, nq = l & 15;
            float4 v = *(const float4*)&B[(size_t)(k0+kk)*F + bn + nq*4];
            Bs[kk][nq*4+0] = f2tf32(v.x);
            Bs[kk][nq*4+1] = f2tf32(v.y);
            Bs[kk][nq*4+2] = f2tf32(v.z);
            Bs[kk][nq*4+3] = f2tf32(v.w);
        }
        __syncthreads();
#pragma unroll
        for (int kk = 0; kk < 32; kk += 8){
            uint32_t bf[4][2];
#pragma unroll
            for (int j=0;j<4;j++){
                bf[j][0] = Bs[kk + ti    ][wn*32 + j*8 + g];
                bf[j][1] = Bs[kk + 4 + ti][wn*32 + j*8 + g];
            }
#pragma unroll
            for (int mi=0;mi<2;mi++){
                int mb = wm*32 + mi*16;
                uint32_t a0 = As[kk + ti    ][mb + g];
                uint32_t a1 = As[kk + ti    ][mb + g + 8];
                uint32_t a2 = As[kk + 4 + ti][mb + g];
                uint32_t a3 = As[kk + 4 + ti][mb + g + 8];
#pragma unroll
                for (int j=0;j<4;j++)
                    mma_tf32(acc[mi][j], a0, a1, a2, a3, bf[j][0], bf[j][1]);
            }
        }
        __syncthreads();
    }

#pragma unroll
    for (int mi=0;mi<2;mi++){
#pragma unroll
        for (int j=0;j<4;j++){
            int c = bn + wn*32 + j*8 + 2*ti;
            float b0 = bias ? bias[c]   : 0.f;
            float b1 = bias ? bias[c+1] : 0.f;
            float4 a = acc[mi][j];
            float2 v0 = make_float2(a.x + b0, a.y + b1);
            float2 v1 = make_float2(a.z + b0, a.w + b1);
            if (act){
                v0.x = fmaxf(v0.x, 0.f); v0.y = fmaxf(v0.y, 0.f);
                v1.x = fmaxf(v1.x, 0.f); v1.y = fmaxf(v1.y, 0.f);
            }
            int r0 = bm + wm*32 + mi*16 + g;
            int r1 = r0 + 8;
            if (r0 < M) *(float2*)&C[(size_t)r0*F + c] = v0;
            if (r1 < M) *(float2*)&C[(size_t)r1*F + c] = v1;
        }
    }
}

// ---------------- fused gather kernels (warp per node, edge-unrolled x2) ----------------
__global__ void gcn_gather_k(const float* __restrict__ h, const float* __restrict__ dinv,
                             const int* __restrict__ rp, const int* __restrict__ ci,
                             const float* __restrict__ bias, float* __restrict__ out, int n)
{
    int w = (blockIdx.x*blockDim.x + threadIdx.x) >> 5;
    if (w >= n) return;
    int lane = threadIdx.x & 31;
    int beg = rp[w], end = rp[w+1];
    float dvd = dinv[w];
    float a0 = dvd * h[(size_t)w*64 + lane];
    float a1 = dvd * h[(size_t)w*64 + 32 + lane];
    int e = beg;
    for (; e + 2 <= end; e += 2){
        int sA = ci[e], sB = ci[e+1];
        float dA = dinv[sA], dB = dinv[sB];
        float hA0 = h[(size_t)sA*64 + lane];
        float hA1 = h[(size_t)sA*64 + 32 + lane];
        float hB0 = h[(size_t)sB*64 + lane];
        float hB1 = h[(size_t)sB*64 + 32 + lane];
        a0 += dA*hA0 + dB*hB0;
        a1 += dA*hA1 + dB*hB1;
    }
    if (e < end){
        int s = ci[e];
        float ds = dinv[s];
        a0 += ds * h[(size_t)s*64 + lane];
        a1 += ds * h[(size_t)s*64 + 32 + lane];
    }
    out[(size_t)w*64 + lane]      = fmaxf(dvd*a0 + bias[lane],    0.f);
    out[(size_t)w*64 + 32 + lane] = fmaxf(dvd*a1 + bias[32+lane], 0.f);
}

__global__ void sage_gather_k(const float* __restrict__ hl, const float* __restrict__ xr,
                              const int* __restrict__ rp, const int* __restrict__ ci,
                              const float* __restrict__ bl, float* __restrict__ out, int n)
{
    int w = (blockIdx.x*blockDim.x + threadIdx.x) >> 5;
    if (w >= n) return;
    int lane = threadIdx.x & 31;
    int beg = rp[w], end = rp[w+1];
    float a0 = 0.f, a1 = 0.f;
    int e = beg;
    for (; e + 2 <= end; e += 2){
        int sA = ci[e], sB = ci[e+1];
        float hA0 = hl[(size_t)sA*64 + lane];
        float hA1 = hl[(size_t)sA*64 + 32 + lane];
        float hB0 = hl[(size_t)sB*64 + lane];
        float hB1 = hl[(size_t)sB*64 + 32 + lane];
        a0 += hA0 + hB0;
        a1 += hA1 + hB1;
    }
    if (e < end){
        int s = ci[e];
        a0 += hl[(size_t)s*64 + lane];
        a1 += hl[(size_t)s*64 + 32 + lane];
    }
    float inv = 1.f / fmaxf((float)(end - beg), 1.f);
    out[(size_t)w*64 + lane]      = fmaxf(a0*inv + bl[lane]    + xr[(size_t)w*64 + lane],      0.f);
    out[(size_t)w*64 + 32 + lane] = fmaxf(a1*inv + bl[32+lane] + xr[(size_t)w*64 + 32 + lane], 0.f);
}

__global__ void gat_scal_k(const float* __restrict__ h, const float* __restrict__ asrc,
                           const float* __restrict__ adst, float* as_, float* ad_,
                           int n, int H, int C){
    int idx = blockIdx.x*blockDim.x + threadIdx.x;
    if (idx >= n*H) return;
    int node = idx / H, hh = idx % H;
    const float* hp = h + (size_t)node*H*C + (size_t)hh*C;
    const float* ap = asrc + hh*C;
    const float* bp = adst + hh*C;
    float s=0.f, d=0.f;
#pragma unroll 8
    for (int c=0;c<C;c++){ float v=hp[c]; s += v*ap[c]; d += v*bp[c]; }
    as_[idx]=s; ad_[idx]=d;
}

__global__ void gat1_gather_k(const float4* __restrict__ h4, const float4* __restrict__ as4,
                              const float4* __restrict__ ad4,
                              const int* __restrict__ rp, const int* __restrict__ ci,
                              const float4* __restrict__ bias4, float4* __restrict__ out4, int n)
{
    int w = (blockIdx.x*blockDim.x + threadIdx.x) >> 5;
    if (w >= n) return;
    int lane = threadIdx.x & 31;
    bool lo = (lane < 16);
    int beg = rp[w], end = rp[w+1];
    float4 ad = ad4[w];
    float adv0 = lo ? ad.x : ad.y;
    float adv1 = lo ? ad.z : ad.w;
    float4 asw = as4[w];
    float es0 = lrelu((lo ? asw.x : asw.y) + adv0);
    float es1 = lrelu((lo ? asw.z : asw.w) + adv1);
    float m0 = es0, m1 = es1;
    {
        int e = beg;
        for (; e + 2 <= end; e += 2){
            float4 aA = as4[ci[e]];
            float4 aB = as4[ci[e+1]];
            m0 = fmaxf(m0, fmaxf(lrelu((lo ? aA.x : aA.y) + adv0),
                                 lrelu((lo ? aB.x : aB.y) + adv0)));
            m1 = fmaxf(m1, fmaxf(lrelu((lo ? aA.z : aA.w) + adv1),
                                 lrelu((lo ? aB.z : aB.w) + adv1)));
        }
        if (e < end){
            float4 a = as4[ci[e]];
            m0 = fmaxf(m0, lrelu((lo ? a.x : a.y) + adv0));
            m1 = fmaxf(m1, lrelu((lo ? a.z : a.w) + adv1));
        }
    }
    float w0 = expf(es0 - m0), w1 = expf(es1 - m1);
    float den0 = w0, den1 = w1;
    float4 hv0 = h4[(size_t)w*64 + lane];
    float4 hv1 = h4[(size_t)w*64 + 32 + lane];
    float4 acc0 = make_float4(w0*hv0.x, w0*hv0.y, w0*hv0.z, w0*hv0.w);
    float4 acc1 = make_float4(w1*hv1.x, w1*hv1.y, w1*hv1.z, w1*hv1.w);
    int e = beg;
    for (; e + 2 <= end; e += 2){
        int sA = ci[e], sB = ci[e+1];
        float4 aA = as4[sA];
        float4 aB = as4[sB];
        float4 vA0 = h4[(size_t)sA*64 + lane];
        float4 vA1 = h4[(size_t)sA*64 + 32 + lane];
        float4 vB0 = h4[(size_t)sB*64 + lane];
        float4 vB1 = h4[(size_t)sB*64 + 32 + lane];
        float wA0 = expf(lrelu((lo ? aA.x : aA.y) + adv0) - m0);
        float wA1 = expf(lrelu((lo ? aA.z : aA.w) + adv1) - m1);
        float wB0 = expf(lrelu((lo ? aB.x : aB.y) + adv0) - m0);
        float wB1 = expf(lrelu((lo ? aB.z : aB.w) + adv1) - m1);
        den0 += wA0 + wB0; den1 += wA1 + wB1;
        acc0.x += wA0*vA0.x + wB0*vB0.x; acc0.y += wA0*vA0.y + wB0*vB0.y;
        acc0.z += wA0*vA0.z + wB0*vB0.z; acc0.w += wA0*vA0.w + wB0*vB0.w;
        acc1.x += wA1*vA1.x + wB1*vB1.x; acc1.y += wA1*vA1.y + wB1*vB1.y;
        acc1.z += wA1*vA1.z + wB1*vB1.z; acc1.w += wA1*vA1.w + wB1*vB1.w;
    }
    if (e < end){
        int s = ci[e];
        float4 a = as4[s];
        float we0 = expf(lrelu((lo ? a.x : a.y) + adv0) - m0);
        float we1 = expf(lrelu((lo ? a.z : a.w) + adv1) - m1);
        den0 += we0; den1 += we1;
        float4 v0 = h4[(size_t)s*64 + lane];
        float4 v1 = h4[(size_t)s*64 + 32 + lane];
        acc0.x += we0*v0.x; acc0.y += we0*v0.y; acc0.z += we0*v0.z; acc0.w += we0*v0.w;
        acc1.x += we1*v1.x; acc1.y += we1*v1.y; acc1.z += we1*v1.z; acc1.w += we1*v1.w;
    }
    float inv0 = 1.f/(den0 + 1e-16f), inv1 = 1.f/(den1 + 1e-16f);
    float4 b0 = bias4[lane], b1 = bias4[32+lane];
    float4 o0, o1;
    o0.x = elu(acc0.x*inv0 + b0.x); o0.y = elu(acc0.y*inv0 + b0.y);
    o0.z = elu(acc0.z*inv0 + b0.z); o0.w = elu(acc0.w*inv0 + b0.w);
    o1.x = elu(acc1.x*inv1 + b1.x); o1.y = elu(acc1.y*inv1 + b1.y);
    o1.z = elu(acc1.z*inv1 + b1.z); o1.w = elu(acc1.w*inv1 + b1.w);
    out4[(size_t)w*64 + lane] = o0;
    out4[(size_t)w*64 + 32 + lane] = o1;
}

__global__ void gat2_gather_k(const float* __restrict__ h, const float* __restrict__ as_,
                              const float* __restrict__ ad_,
                              const int* __restrict__ rp, const int* __restrict__ ci,
                              const float* __restrict__ bias, float* __restrict__ out, int n)
{
    int w = (blockIdx.x*blockDim.x + threadIdx.x) >> 5;
    if (w >= n) return;
    int lane = threadIdx.x & 31;
    int beg = rp[w], end = rp[w+1];
    float adv = ad_[w];
    float es = lrelu(as_[w] + adv);
    float m = es;
    {
        int e = beg;
        for (; e + 2 <= end; e += 2){
            float eA = lrelu(as_[ci[e]]   + adv);
            float eB = lrelu(as_[ci[e+1]] + adv);
            m = fmaxf(m, fmaxf(eA, eB));
        }
        if (e < end) m = fmaxf(m, lrelu(as_[ci[e]] + adv));
    }
    float w0 = expf(es - m);
    float den = w0;
    float a0 = w0 * h[(size_t)w*64 + lane];
    float a1 = w0 * h[(size_t)w*64 + 32 + lane];
    int e = beg;
    for (; e + 2 <= end; e += 2){
        int sA = ci[e], sB = ci[e+1];
        float wA = expf(lrelu(as_[sA] + adv) - m);
        float wB = expf(lrelu(as_[sB] + adv) - m);
        float hA0 = h[(size_t)sA*64 + lane];
        float hA1 = h[(size_t)sA*64 + 32 + lane];
        float hB0 = h[(size_t)sB*64 + lane];
        float hB1 = h[(size_t)sB*64 + 32 + lane];
        den += wA + wB;
        a0 += wA*hA0 + wB*hB0;
        a1 += wA*hA1 + wB*hB1;
    }
    if (e < end){
        int s = ci[e];
        float we = expf(lrelu(as_[s] + adv) - m);
        den += we;
        a0 += we * h[(size_t)s*64 + lane];
        a1 += we * h[(size_t)s*64 + 32 + lane];
    }
    float inv = 1.f/(den + 1e-16f);
    out[(size_t)w*64 + lane]      = elu(a0*inv + bias[lane]);
    out[(size_t)w*64 + 32 + lane] = elu(a1*inv + bias[32+lane]);
}

// ---------------- BatchNorm ----------------
__global__ void bn_stats_k(const float* __restrict__ x, float* gsum, float* gsq, int total){
    __shared__ float ss[256];
    __shared__ float sq[256];
    int tid = threadIdx.x;
    float s = 0.f, q = 0.f;
    for (int i = blockIdx.x*256 + tid; i < total; i += gridDim.x*256){
        float v = x[i];
        s += v; q += v*v;
    }
    ss[tid] = s; sq[tid] = q;
    __syncthreads();
    if (tid < 64){
        int c = tid & 63;
        float ts = ss[tid] + ss[tid+64] + ss[tid+128] + ss[tid+192];
        float tq = sq[tid] + sq[tid+64] + sq[tid+128] + sq[tid+192];
        atomicAdd(&gsum[c], ts);
        atomicAdd(&gsq[c], tq);
    }
}
// computes mean/var AND re-zeroes accumulators (deterministic across replays)
__global__ void bn_final_k(float* gsum, float* gsq, float* mean, float* var, int n){
    int c = threadIdx.x;
    if (c < 64){
        float m = gsum[c] / (float)n;
        mean[c] = m;
        var[c] = gsq[c] / (float)n - m*m;
        gsum[c] = 0.f;
        gsq[c]  = 0.f;
    }
}
__global__ void bn_apply_k(const float* __restrict__ x, const float* __restrict__ mean,
                           const float* __restrict__ var, const float* __restrict__ g,
                           const float* __restrict__ b, float* cat, int n, int off){
    int i = blockIdx.x*blockDim.x + threadIdx.x;
    if (i >= n*64) return;
    int c = i & 63;
    float v = (x[i] - mean[c]) * rsqrtf(var[c] + 1e-5f) * g[c] + b[c];
    cat[(size_t)(i >> 6)*192 + off + c] = v;
}

// ---------------- fc2: [n,64] @ [64,2] + b ----------------
__global__ void fc2_k(const float* __restrict__ in, const float* __restrict__ w,
                      const float* __restrict__ b, float* __restrict__ out, int n){
    __shared__ float ws[128];
    if (threadIdx.x < 128) ws[threadIdx.x] = w[threadIdx.x];
    __syncthreads();
    int i = blockIdx.x*blockDim.x + threadIdx.x;
    if (i >= n) return;
    const float4* r = (const float4*)(in + (size_t)i*64);
    float s0 = 0.f, s1 = 0.f;
#pragma unroll
    for (int k=0;k<16;k++){
        float4 v = r[k];
        s0 += v.x*ws[(k*4+0)*2] + v.y*ws[(k*4+1)*2] + v.z*ws[(k*4+2)*2] + v.w*ws[(k*4+3)*2];
        s1 += v.x*ws[(k*4+0)*2+1] + v.y*ws[(k*4+1)*2+1] + v.z*ws[(k*4+2)*2+1] + v.w*ws[(k*4+3)*2+1];
    }
    out[(size_t)i*2]   = s0 + b[0];
    out[(size_t)i*2+1] = s1 + b[1];
}

// ---------------- host orchestration ----------------
static inline float* symf(const void* s){ void* p=nullptr; cudaGetSymbolAddress(&p, s); return (float*)p; }
static inline int*   symi(const void* s){ void* p=nullptr; cudaGetSymbolAddress(&p, s); return (int*)p; }

extern "C" void kernel_launch(void* const* d_in, const int* in_sizes, int n_in,
                              void* d_out, int out_size)
{
    const float* x        = (const float*)d_in[0];
    const int*   eidx     = (const int*)  d_in[1];
    const float* gcn1_w   = (const float*)d_in[2];
    const float* gcn1_b   = (const float*)d_in[3];
    const float* gcn2_w   = (const float*)d_in[4];
    const float* gcn2_b   = (const float*)d_in[5];
    const float* gat1_w   = (const float*)d_in[6];
    const float* gat1_as  = (const float*)d_in[7];
    const float* gat1_ad  = (const float*)d_in[8];
    const float* gat1_b   = (const float*)d_in[9];
    const float* gat2_w   = (const float*)d_in[10];
    const float* gat2_as  = (const float*)d_in[11];
    const float* gat2_ad  = (const float*)d_in[12];
    const float* gat2_b   = (const float*)d_in[13];
    const float* sage1_wl = (const float*)d_in[14];
    const float* sage1_bl = (const float*)d_in[15];
    const float* sage1_wr = (const float*)d_in[16];
    const float* sage2_wl = (const float*)d_in[17];
    const float* sage2_bl = (const float*)d_in[18];
    const float* sage2_wr = (const float*)d_in[19];
    const float* bng_g    = (const float*)d_in[20];
    const float* bng_b    = (const float*)d_in[21];
    const float* bna_g    = (const float*)d_in[22];
    const float* bna_b    = (const float*)d_in[23];
    const float* bns_g    = (const float*)d_in[24];
    const float* bns_b    = (const float*)d_in[25];
    const float* fc1_w    = (const float*)d_in[26];
    const float* fc1_b    = (const float*)d_in[27];
    const float* fc2_w    = (const float*)d_in[28];
    const float* fc2_b    = (const float*)d_in[29];
    float* out = (float*)d_out;

    const int n = in_sizes[0] / 128;
    const int E = in_sizes[1] / 2;
    const int* src = eidx;
    const int* dst = eidx + E;

    float* hg   = symf(d_hg);
    float* g1   = symf(d_g1);
    float* g2   = symf(d_g2);
    float* hgat = symf(d_hgat);
    float* a1   = symf(d_a1);
    float* a2   = symf(d_a2);
    float* hsl  = symf(d_hsl);
    float* hsr  = symf(d_hsr);
    float* s1b  = symf(d_s1);
    float* s2b  = symf(d_s2);
    float* cat  = symf(d_cat);
    float* fc1o = symf(d_fc1o);
    float* as_  = symf(d_as);
    float* ad_  = symf(d_ad);
    float* dinv = symf(d_dinv);
    int*   cnt  = symi(d_cnt);
    int*   rp   = symi(d_rp);
    int*   cur  = symi(d_cur);
    int*   ci   = symi(d_ci);
    float* bsum = symf(d_bnsum);
    float* bsq  = symf(d_bnsq);
    float* bmean= symf(d_bnmean);
    float* bvar = symf(d_bnvar);

    // side streams / events, created once (host resources only; identical
    // captured work on every call)
    static cudaStream_t st1 = nullptr, st2 = nullptr;
    static cudaEvent_t evRoot = nullptr, evCSR = nullptr, evGCN = nullptr, evSAGE = nullptr;
    if (!st1){
        cudaStreamCreateWithFlags(&st1, cudaStreamNonBlocking);
        cudaStreamCreateWithFlags(&st2, cudaStreamNonBlocking);
        cudaEventCreateWithFlags(&evRoot, cudaEventDisableTiming);
        cudaEventCreateWithFlags(&evCSR,  cudaEventDisableTiming);
        cudaEventCreateWithFlags(&evGCN,  cudaEventDisableTiming);
        cudaEventCreateWithFlags(&evSAGE, cudaEventDisableTiming);
    }

    const int T = 256;
    auto B  = [](int cnt_){ return dim3(CDIV(cnt_, 256)); };
    auto BW = [n](){ return dim3(CDIV(n*32, 256)); };
    auto GG = [n](int F){ return dim3(CDIV(n,128), F/64); };

    // fork
    cudaEventRecord(evRoot, 0);
    cudaStreamWaitEvent(st1, evRoot, 0);
    cudaStreamWaitEvent(st2, evRoot, 0);

    // ---- st1: CSR build + GCN branch ----
    izero_k   <<<B(n), T, 0, st1>>>(cnt, n);
    hist_k    <<<B(E), T, 0, st1>>>(dst, cnt, E);
    scan_k    <<<1, 1024, 0, st1>>>(cnt, rp, cur, n);
    csr_fill_k<<<B(E), T, 0, st1>>>(src, dst, cur, ci, E);
    dinv_k    <<<B(n), T, 0, st1>>>(cnt, dinv, n);
    cudaEventRecord(evCSR, st1);

    gemm_mma_k  <<<GG(64), T, 0, st1>>>(x, gcn1_w, hg, nullptr, n, 128, 64, 0);
    gcn_gather_k<<<BW(), T, 0, st1>>>(hg, dinv, rp, ci, gcn1_b, g1, n);
    gemm_mma_k  <<<GG(64), T, 0, st1>>>(g1, gcn2_w, hg, nullptr, n, 64, 64, 0);
    gcn_gather_k<<<BW(), T, 0, st1>>>(hg, dinv, rp, ci, gcn2_b, g2, n);
    bn_stats_k  <<<256, T, 0, st1>>>(g2, bsum, bsq, n*64);
    bn_final_k  <<<1, 64, 0, st1>>>(bsum, bsq, bmean, bvar, n);
    bn_apply_k  <<<B(n*64), T, 0, st1>>>(g2, bmean, bvar, bng_g, bng_b, cat, n, 0);
    cudaEventRecord(evGCN, st1);

    // ---- st2: SAGE branch ----
    gemm_mma_k<<<GG(64), T, 0, st2>>>(x, sage1_wl, hsl, nullptr, n, 128, 64, 0);
    gemm_mma_k<<<GG(64), T, 0, st2>>>(x, sage1_wr, hsr, nullptr, n, 128, 64, 0);
    cudaStreamWaitEvent(st2, evCSR, 0);
    sage_gather_k<<<BW(), T, 0, st2>>>(hsl, hsr, rp, ci, sage1_bl, s1b, n);
    gemm_mma_k<<<GG(64), T, 0, st2>>>(s1b, sage2_wl, hsl, nullptr, n, 64, 64, 0);
    gemm_mma_k<<<GG(64), T, 0, st2>>>(s1b, sage2_wr, hsr, nullptr, n, 64, 64, 0);
    sage_gather_k<<<BW(), T, 0, st2>>>(hsl, hsr, rp, ci, sage2_bl, s2b, n);
    bn_stats_k<<<256, T, 0, st2>>>(s2b, bsum+128, bsq+128, n*64);
    bn_final_k<<<1, 64, 0, st2>>>(bsum+128, bsq+128, bmean+128, bvar+128, n);
    bn_apply_k<<<B(n*64), T, 0, st2>>>(s2b, bmean+128, bvar+128, bns_g, bns_b, cat, n, 128);
    cudaEventRecord(evSAGE, st2);

    // ---- main stream: GAT branch (longest) ----
    gemm_mma_k<<<GG(256), T>>>(x, gat1_w, hgat, nullptr, n, 128, 256, 0);
    gat_scal_k<<<B(n*4), T>>>(hgat, gat1_as, gat1_ad, as_, ad_, n, 4, 64);
    cudaStreamWaitEvent(0, evCSR, 0);
    gat1_gather_k<<<BW(), T>>>((const float4*)hgat, (const float4*)as_, (const float4*)ad_,
                               rp, ci, (const float4*)gat1_b, (float4*)a1, n);
    gemm_mma_k<<<GG(64), T>>>(a1, gat2_w, hgat, nullptr, n, 256, 64, 0);
    gat_scal_k<<<B(n), T>>>(hgat, gat2_as, gat2_ad, as_, ad_, n, 1, 64);
    gat2_gather_k<<<BW(), T>>>(hgat, as_, ad_, rp, ci, gat2_b, a2, n);
    bn_stats_k<<<256, T>>>(a2, bsum+64, bsq+64, n*64);
    bn_final_k<<<1, 64>>>(bsum+64, bsq+64, bmean+64, bvar+64, n);
    bn_apply_k<<<B(n*64), T>>>(a2, bmean+64, bvar+64, bna_g, bna_b, cat, n, 64);

    // join + head
    cudaStreamWaitEvent(0, evGCN, 0);
    cudaStreamWaitEvent(0, evSAGE, 0);
    gemm_mma_k<<<GG(64), T>>>(cat, fc1_w, fc1o, fc1_b, n, 192, 64, 1);
    fc2_k<<<B(n), T>>>(fc1o, fc2_w, fc2_b, out, n);
}